// round 11
// baseline (speedup 1.0000x reference)
#include <cuda_runtime.h>
#include <cuda_bf16.h>
#include <cstdint>

// Problem constants
#define BDIM 2
#define VDIM 8
#define PDIM 4096
#define DDIM 1024
#define NREF 256
#define EN   16384
#define NCAND 8

// Scratch (device globals: allocation-free)
__device__ __nv_bfloat16 g_bbf[BDIM * EN * DDIM];     // 67 MB bf16 extra frames
__device__ __nv_bfloat16 g_abf[BDIM * NREF * DDIM];   // 1 MB bf16 gathered refs
__device__ float g_inv[BDIM * EN];
__device__ __nv_bfloat16 g_sim[BDIM * NREF * EN];     // 16.8 MB bf16 sims
__device__ int   g_topk[BDIM * NREF * 4];
__device__ float g_accum[3];
__device__ unsigned g_done;

__constant__ int c_ST[3] = {2, 4, 6};   // SHARED_TEACHER
__constant__ int c_SS[3] = {1, 2, 3};   // SHARED_STUDENT

__device__ __forceinline__ void ins4(float x, int e, float* v, int* id) {
    if (x <= v[3]) return;
    v[3] = x; id[3] = e;
    #pragma unroll
    for (int j = 3; j >= 1; j--) {
        if (v[j] > v[j - 1]) {
            float tv = v[j]; v[j] = v[j - 1]; v[j - 1] = tv;
            int ti = id[j]; id[j] = id[j - 1]; id[j - 1] = ti;
        }
    }
}

__device__ __forceinline__ void ins8(float x, int e, float* v, int* id) {
    if (x <= v[7]) return;
    v[7] = x; id[7] = e;
    #pragma unroll
    for (int j = 7; j >= 1; j--) {
        if (v[j] > v[j - 1]) {
            float tv = v[j]; v[j] = v[j - 1]; v[j - 1] = tv;
            int ti = id[j]; id[j] = id[j - 1]; id[j - 1] = ti;
        }
    }
}

// ---------------------------------------------------------------------------
// K0: one-pass f32->bf16 convert (+ exact f32 inverse norms for extra rows)
// ---------------------------------------------------------------------------
__global__ void __launch_bounds__(128)
k_convert(const float* __restrict__ teacher, const int* __restrict__ ref_perm) {
    const int id  = blockIdx.x;
    const int tid = threadIdx.x;

    const float* src;
    __nv_bfloat16* dst;
    bool donorm;
    int nidx = 0;
    if (id < BDIM * EN) {
        int b = id >> 14, e = id & (EN - 1);
        int v = 2 * (e >> 12) + 1, p = e & (PDIM - 1);
        src = teacher + ((size_t)(b * VDIM + v) * PDIM + p) * DDIM;
        dst = g_bbf + (size_t)id * DDIM;
        donorm = true; nidx = id;
    } else {
        int t = id - BDIM * EN;
        int b = t >> 8, r = t & 255;
        src = teacher + ((size_t)(b * VDIM) * PDIM + ref_perm[r]) * DDIM;
        dst = g_abf + (size_t)t * DDIM;
        donorm = false;
    }

    float4 x0 = ((const float4*)src)[tid * 2];
    float4 x1 = ((const float4*)src)[tid * 2 + 1];
    __nv_bfloat162 h0, h1, h2, h3;
    h0.x = __float2bfloat16(x0.x); h0.y = __float2bfloat16(x0.y);
    h1.x = __float2bfloat16(x0.z); h1.y = __float2bfloat16(x0.w);
    h2.x = __float2bfloat16(x1.x); h2.y = __float2bfloat16(x1.y);
    h3.x = __float2bfloat16(x1.z); h3.y = __float2bfloat16(x1.w);
    uint4 pk;
    pk.x = *(uint32_t*)&h0; pk.y = *(uint32_t*)&h1;
    pk.z = *(uint32_t*)&h2; pk.w = *(uint32_t*)&h3;
    ((uint4*)dst)[tid] = pk;

    if (donorm) {
        float ss = x0.x * x0.x + x0.y * x0.y + x0.z * x0.z + x0.w * x0.w
                 + x1.x * x1.x + x1.y * x1.y + x1.z * x1.z + x1.w * x1.w;
        #pragma unroll
        for (int o = 16; o; o >>= 1) ss += __shfl_xor_sync(0xffffffffu, ss, o);
        __shared__ float sh[4];
        if ((tid & 31) == 0) sh[tid >> 5] = ss;
        __syncthreads();
        if (tid == 0) {
            float t = sh[0] + sh[1] + sh[2] + sh[3];
            g_inv[nidx] = 1.0f / fmaxf(sqrtf(t), 1e-12f);
        }
    }
}

// ---------------------------------------------------------------------------
// K1: bf16 GEMM, cp.async 3-stage pipeline, 256x128 CTA tile (M covers ALL
//     refs -> B read from DRAM exactly once), BK=32, 512 threads, 16 warps
//     (4x4), warp tile 64x32.
// ---------------------------------------------------------------------------
#define NKT   (DDIM / 32)        // 32 k-tiles
#define STAGES 3
#define AROWB 80                 // 64 data bytes + 16 pad per row-chunk
#define A_BYTES (256 * AROWB)    // 20480
#define STAGE_BYTES (384 * AROWB)            // 30720 (A 256 rows + B 128 rows)
#define GEMM_SMEM (STAGES * STAGE_BYTES)     // 92160

__device__ __forceinline__ void cp_async16(uint32_t dst, const void* src) {
    asm volatile("cp.async.cg.shared.global [%0], [%1], 16;" :: "r"(dst), "l"(src));
}

__global__ void __launch_bounds__(512, 1)
k_gemm() {
    extern __shared__ __align__(16) uint8_t smem[];
    __shared__ float s_inv[128];

    const int b     = blockIdx.z;
    const int ebase = blockIdx.x * 128;
    const int tid   = threadIdx.x;
    const int lane  = tid & 31;
    const int wid   = tid >> 5;          // 0..15
    const int wm    = (wid >> 2) * 64;   // 4 M-groups of 64
    const int wn    = (wid & 3) * 32;    // 4 N-groups of 32
    const uint32_t sbase = (uint32_t)__cvta_generic_to_shared(smem);

    // loaders: flat chunk index c = tid + s*512, c in [0,1536)
    //   row = c >> 2 (0..383), off16 = (c & 3) * 16
    //   rows [0,256) = A (g_abf), rows [256,384) = B (g_bbf)
    const char* gsrc[3];
    uint32_t    soff[3];
    #pragma unroll
    for (int s = 0; s < 3; s++) {
        int c = tid + s * 512;
        int row = c >> 2;
        int off16 = (c & 3) * 16;
        if (row < 256)
            gsrc[s] = (const char*)(g_abf + ((size_t)(b * NREF + row)) * DDIM) + off16;
        else
            gsrc[s] = (const char*)(g_bbf + ((size_t)(b * EN + ebase + (row - 256))) * DDIM) + off16;
        soff[s] = (uint32_t)(row * AROWB + off16);
    }

    float acc[4][4][4];
    #pragma unroll
    for (int i = 0; i < 4; i++)
        #pragma unroll
        for (int j = 0; j < 4; j++)
            #pragma unroll
            for (int k = 0; k < 4; k++) acc[i][j][k] = 0.f;

    // ldmatrix lane addressing (byte offsets within a stage)
    const int xr = (lane & 7) + ((lane >> 3) & 1) * 8;
    const int xk = (lane >> 4) * 16;
    uint32_t a_off[4], b_off[2];
    #pragma unroll
    for (int mi = 0; mi < 4; mi++)
        a_off[mi] = (uint32_t)((wm + mi * 16 + xr) * AROWB + xk);
    #pragma unroll
    for (int nj = 0; nj < 2; nj++)
        b_off[nj] = A_BYTES + (uint32_t)((wn + nj * 16 + xr) * AROWB + xk);

    // prologue: issue stages 0..STAGES-2
    #pragma unroll
    for (int s = 0; s < STAGES - 1; s++) {
        #pragma unroll
        for (int q = 0; q < 3; q++)
            cp_async16(sbase + s * STAGE_BYTES + soff[q], gsrc[q] + s * 64);
        asm volatile("cp.async.commit_group;");
    }

    for (int kt = 0; kt < NKT; kt++) {
        asm volatile("cp.async.wait_group %0;" :: "n"(STAGES - 2));
        __syncthreads();

        int wst = kt + STAGES - 1;
        if (wst < NKT) {
            int st = wst % STAGES;
            #pragma unroll
            for (int q = 0; q < 3; q++)
                cp_async16(sbase + st * STAGE_BYTES + soff[q], gsrc[q] + wst * 64);
        }
        asm volatile("cp.async.commit_group;");

        const uint32_t stg = (kt % STAGES) * STAGE_BYTES;
        #pragma unroll
        for (int ks = 0; ks < 64; ks += 32) {
            uint32_t af[4][4], bf[2][4];
            #pragma unroll
            for (int mi = 0; mi < 4; mi++) {
                asm volatile("ldmatrix.sync.aligned.m8n8.x4.shared.b16 {%0,%1,%2,%3}, [%4];"
                    : "=r"(af[mi][0]), "=r"(af[mi][1]), "=r"(af[mi][2]), "=r"(af[mi][3])
                    : "r"(sbase + stg + a_off[mi] + ks));
            }
            #pragma unroll
            for (int nj = 0; nj < 2; nj++) {
                asm volatile("ldmatrix.sync.aligned.m8n8.x4.shared.b16 {%0,%1,%2,%3}, [%4];"
                    : "=r"(bf[nj][0]), "=r"(bf[nj][1]), "=r"(bf[nj][2]), "=r"(bf[nj][3])
                    : "r"(sbase + stg + b_off[nj] + ks));
            }
            #pragma unroll
            for (int mi = 0; mi < 4; mi++) {
                #pragma unroll
                for (int nj = 0; nj < 4; nj++) {
                    uint32_t bb0 = bf[nj >> 1][nj & 1];
                    uint32_t bb1 = bf[nj >> 1][(nj & 1) + 2];
                    asm volatile(
                        "mma.sync.aligned.m16n8k16.row.col.f32.bf16.bf16.f32 "
                        "{%0,%1,%2,%3}, {%4,%5,%6,%7}, {%8,%9}, {%0,%1,%2,%3};"
                        : "+f"(acc[mi][nj][0]), "+f"(acc[mi][nj][1]),
                          "+f"(acc[mi][nj][2]), "+f"(acc[mi][nj][3])
                        : "r"(af[mi][0]), "r"(af[mi][1]), "r"(af[mi][2]), "r"(af[mi][3]),
                          "r"(bb0), "r"(bb1));
                }
            }
        }
    }

    // inverse norms for this column tile (exact, precomputed from f32)
    __syncthreads();
    if (tid < 128) s_inv[tid] = g_inv[b * EN + ebase + tid];
    __syncthreads();

    // epilogue: scale by inv_norm[e], write bf16 sims (4B packed stores)
    #pragma unroll
    for (int mi = 0; mi < 4; mi++) {
        int r = wm + mi * 16 + (lane >> 2);
        __nv_bfloat16* orow = g_sim + ((size_t)(b * NREF + r)) * EN + ebase;
        #pragma unroll
        for (int nj = 0; nj < 4; nj++) {
            int c = wn + nj * 8 + (lane & 3) * 2;
            __nv_bfloat162 h0, h1;
            h0.x = __float2bfloat16(acc[mi][nj][0] * s_inv[c]);
            h0.y = __float2bfloat16(acc[mi][nj][1] * s_inv[c + 1]);
            h1.x = __float2bfloat16(acc[mi][nj][2] * s_inv[c]);
            h1.y = __float2bfloat16(acc[mi][nj][3] * s_inv[c + 1]);
            *(uint32_t*)(orow + c)          = *(uint32_t*)&h0;
            *(uint32_t*)(orow + 8 * EN + c) = *(uint32_t*)&h1;
        }
    }
}

// ---------------------------------------------------------------------------
// K2: per (b,r): top-8 candidates from bf16 sims (vectorized 16B loads),
//     then exact fp32 re-rank -> exact top-4 indices.
// ---------------------------------------------------------------------------
__global__ void __launch_bounds__(256)
k_select(const float* __restrict__ teacher, const int* __restrict__ ref_perm) {
    int r = blockIdx.x, b = blockIdx.y, tid = threadIdx.x;
    int w = tid >> 5, lane = tid & 31;
    const __nv_bfloat16* row = g_sim + ((size_t)(b * NREF + r)) * EN;

    if (r == 0 && b == 0 && tid < 3) g_accum[tid] = 0.f;

    float v[4] = {-3.4e38f, -3.4e38f, -3.4e38f, -3.4e38f};
    int id[4] = {0, 0, 0, 0};
    #pragma unroll
    for (int k = 0; k < 8; k++) {
        int base = (k * 256 + tid) * 8;
        uint4 pk = *(const uint4*)(row + base);
        uint32_t uu[4] = {pk.x, pk.y, pk.z, pk.w};
        #pragma unroll
        for (int q = 0; q < 4; q++) {
            __nv_bfloat162 h = *(__nv_bfloat162*)&uu[q];
            ins4(__bfloat162float(h.x), base + q * 2,     v, id);
            ins4(__bfloat162float(h.y), base + q * 2 + 1, v, id);
        }
    }

    __shared__ float sv[1024];
    __shared__ int   si[1024];
    __shared__ int   s_cand[NCAND];
    __shared__ float s_sim[NCAND];
    __shared__ int   s_e[NCAND];

    #pragma unroll
    for (int j = 0; j < 4; j++) { sv[tid * 4 + j] = v[j]; si[tid * 4 + j] = id[j]; }
    __syncthreads();

    if (tid < 32) {
        float v2[4] = {-3.4e38f, -3.4e38f, -3.4e38f, -3.4e38f};
        int id2[4] = {0, 0, 0, 0};
        for (int t = tid * 32; t < tid * 32 + 32; t++) ins4(sv[t], si[t], v2, id2);
        __syncwarp();
        #pragma unroll
        for (int j = 0; j < 4; j++) { sv[tid * 4 + j] = v2[j]; si[tid * 4 + j] = id2[j]; }
        __syncwarp();
        if (tid == 0) {
            float v3[8]; int id3[8];
            #pragma unroll
            for (int j = 0; j < 8; j++) { v3[j] = -3.4e38f; id3[j] = 0; }
            for (int t = 0; t < 128; t++) ins8(sv[t], si[t], v3, id3);
            #pragma unroll
            for (int j = 0; j < 8; j++) s_cand[j] = id3[j];
        }
    }
    __syncthreads();

    int e = s_cand[w];
    int vv = 2 * (e >> 12) + 1, p = e & (PDIM - 1);
    const float* er = teacher + ((size_t)(b * VDIM + vv) * PDIM + p) * DDIM;
    const float* rr = teacher + ((size_t)(b * VDIM) * PDIM + ref_perm[r]) * DDIM;

    float dot = 0.f, ss = 0.f;
    #pragma unroll
    for (int j = 0; j < 8; j++) {
        int idx = lane * 4 + j * 128;
        float4 x = *(const float4*)(er + idx);
        float4 y = *(const float4*)(rr + idx);
        dot += x.x * y.x + x.y * y.y + x.z * y.z + x.w * y.w;
        ss  += x.x * x.x + x.y * x.y + x.z * x.z + x.w * x.w;
    }
    #pragma unroll
    for (int o = 16; o; o >>= 1) {
        dot += __shfl_xor_sync(0xffffffffu, dot, o);
        ss  += __shfl_xor_sync(0xffffffffu, ss, o);
    }
    if (lane == 0) {
        s_sim[w] = dot / fmaxf(sqrtf(ss), 1e-12f);
        s_e[w] = e;
    }
    __syncthreads();

    if (tid == 0) {
        bool used[NCAND] = {false, false, false, false, false, false, false, false};
        #pragma unroll
        for (int j = 0; j < 4; j++) {
            int best = -1;
            float bvv = -3.4e38f; int be = 0x7fffffff;
            for (int t = 0; t < NCAND; t++) {
                if (used[t]) continue;
                if (s_sim[t] > bvv || (s_sim[t] == bvv && s_e[t] < be)) {
                    bvv = s_sim[t]; be = s_e[t]; best = t;
                }
            }
            used[best] = true;
            g_topk[(b * NREF + r) * 4 + j] = s_e[best];
        }
    }
}

// ---------------------------------------------------------------------------
// K3: KL + smooth-L1 losses, 64 threads per row-pair, fast-math exp/log;
//     last-arriving block writes the final scalar.
// ---------------------------------------------------------------------------
__global__ void __launch_bounds__(256)
k_loss(const float* __restrict__ teacher, const float* __restrict__ student,
       const int* __restrict__ ref_perm, const int* __restrict__ shared_perm,
       float* __restrict__ out) {
    __shared__ float sacc[3];
    __shared__ float r0[4][2], r1[4][2];
    int tid = threadIdx.x;
    if (tid < 3) sacc[tid] = 0.f;

    int grp  = tid >> 6;
    int sub  = tid & 63;
    int w2   = (tid >> 5) & 1;
    int lane = tid & 31;
    int w    = blockIdx.x * 4 + grp;

    const float *pa, *pb, *pc, *pd;
    int target;
    if (w < 1536) {
        target = 0;
        int i = w / 512, rem = w & 511;
        int b = rem >> 8, r = rem & 255;
        int rp = ref_perm[r], sp = shared_perm[r];
        pa = teacher + ((size_t)(b * VDIM) * PDIM + rp) * DDIM;
        pb = teacher + ((size_t)(b * VDIM + c_ST[i]) * PDIM + sp) * DDIM;
        pc = student + ((size_t)(b * 4) * PDIM + rp) * DDIM;
        pd = student + ((size_t)(b * 4 + c_SS[i]) * PDIM + sp) * DDIM;
    } else if (w < 3584) {
        target = 1;
        int t = w - 1536;
        int b = t >> 10, rem = t & 1023;
        int r = rem >> 2, k = rem & 3;
        int rp = ref_perm[r];
        int e = g_topk[((b << 8) + r) * 4 + k];
        int v = 2 * (e >> 12) + 1, p = e & (PDIM - 1);
        pa = teacher + ((size_t)(b * VDIM) * PDIM + rp) * DDIM;
        pc = student + ((size_t)(b * 4) * PDIM + rp) * DDIM;
        pb = pd = teacher + ((size_t)(b * VDIM + v) * PDIM + p) * DDIM;
    } else {
        target = 2;
        int t = w - 3584;
        int i = t >> 11, rem = t & 2047;
        int b = rem >> 10, r = (rem >> 2) & 255, k = rem & 3;
        int sp = shared_perm[r];
        int e = g_topk[((b << 8) + r) * 4 + k];
        int v = 2 * (e >> 12) + 1, p = e & (PDIM - 1);
        pa = teacher + ((size_t)(b * VDIM + c_ST[i]) * PDIM + sp) * DDIM;
        pc = student + ((size_t)(b * 4 + c_SS[i]) * PDIM + sp) * DDIM;
        pb = pd = teacher + ((size_t)(b * VDIM + v) * PDIM + p) * DDIM;
    }

    float dt[16], ds[16];
    bool same = (pb == pd);
    #pragma unroll
    for (int j = 0; j < 4; j++) {
        int idx = sub * 4 + j * 256;
        float4 A  = *(const float4*)(pa + idx);
        float4 Bv = *(const float4*)(pb + idx);
        float4 C  = *(const float4*)(pc + idx);
        float4 Dv = same ? Bv : *(const float4*)(pd + idx);
        dt[4 * j + 0] = A.x - Bv.x; dt[4 * j + 1] = A.y - Bv.y;
        dt[4 * j + 2] = A.z - Bv.z; dt[4 * j + 3] = A.w - Bv.w;
        ds[4 * j + 0] = C.x - Dv.x; ds[4 * j + 1] = C.y - Dv.y;
        ds[4 * j + 2] = C.z - Dv.z; ds[4 * j + 3] = C.w - Dv.w;
    }

    float mt = -3.4e38f, ms = -3.4e38f;
    #pragma unroll
    for (int i = 0; i < 16; i++) { mt = fmaxf(mt, dt[i]); ms = fmaxf(ms, ds[i]); }
    #pragma unroll
    for (int o = 16; o; o >>= 1) {
        mt = fmaxf(mt, __shfl_xor_sync(0xffffffffu, mt, o));
        ms = fmaxf(ms, __shfl_xor_sync(0xffffffffu, ms, o));
    }
    if (lane == 0) { r0[grp][w2] = mt; r1[grp][w2] = ms; }
    __syncthreads();
    mt = fmaxf(r0[grp][0], r0[grp][1]);
    ms = fmaxf(r1[grp][0], r1[grp][1]);

    float st = 0.f, ssum = 0.f;
    #pragma unroll
    for (int i = 0; i < 16; i++) { st += __expf(dt[i] - mt); ssum += __expf(ds[i] - ms); }
    #pragma unroll
    for (int o = 16; o; o >>= 1) {
        st   += __shfl_xor_sync(0xffffffffu, st, o);
        ssum += __shfl_xor_sync(0xffffffffu, ssum, o);
    }
    __syncthreads();
    if (lane == 0) { r0[grp][w2] = st; r1[grp][w2] = ssum; }
    __syncthreads();
    float lset = mt + __logf(r0[grp][0] + r0[grp][1]);
    float lses = ms + __logf(r1[grp][0] + r1[grp][1]);

    float acc = 0.f;
    #pragma unroll
    for (int i = 0; i < 16; i++) acc += __expf(dt[i] - lset) * (dt[i] - ds[i]);
    #pragma unroll
    for (int o = 16; o; o >>= 1) acc += __shfl_xor_sync(0xffffffffu, acc, o);
    __syncthreads();
    if (lane == 0) r0[grp][w2] = acc;
    __syncthreads();

    if (sub == 0) {
        float kl = (r0[grp][0] + r0[grp][1]) - lset + lses;
        float ax = fabsf(kl);
        float sl = (ax < 0.5f) ? kl * kl : (ax - 0.25f);   // smooth_l1, beta=0.5
        atomicAdd(&sacc[target], sl);
    }
    __syncthreads();
    if (tid < 3) atomicAdd(&g_accum[tid], sacc[tid]);

    // last-arriving block folds the final combine
    __syncthreads();
    if (tid == 0) {
        __threadfence();
        unsigned t = atomicAdd(&g_done, 1);
        if (t == gridDim.x - 1) {
            __threadfence();
            out[0] = g_accum[0] * (1.0f / 1536.0f)
                   + g_accum[1] * (1.0f / 2048.0f)
                   + g_accum[2] * (1.0f / 6144.0f);
            g_done = 0;
        }
    }
}

// ---------------------------------------------------------------------------
extern "C" void kernel_launch(void* const* d_in, const int* in_sizes, int n_in,
                              void* d_out, int out_size) {
    const float* teacher     = (const float*)d_in[0];
    const float* student     = (const float*)d_in[1];
    const int*   ref_perm    = (const int*)d_in[2];
    const int*   shared_perm = (const int*)d_in[3];
    float* out = (float*)d_out;

    cudaFuncSetAttribute(k_gemm, cudaFuncAttributeMaxDynamicSharedMemorySize, GEMM_SMEM);

    k_convert<<<BDIM * EN + BDIM * NREF, 128>>>(teacher, ref_perm);
    k_gemm<<<dim3(EN / 128, 1, BDIM), 512, GEMM_SMEM>>>();
    k_select<<<dim3(NREF, BDIM), 256>>>(teacher, ref_perm);
    k_loss<<<9728 / 4, 256>>>(teacher, student, ref_perm, shared_perm, out);
}

// round 12
// speedup vs baseline: 1.0662x; 1.0662x over previous
#include <cuda_runtime.h>
#include <cuda_bf16.h>
#include <cstdint>

// Problem constants
#define BDIM 2
#define VDIM 8
#define PDIM 4096
#define DDIM 1024
#define NREF 256
#define EN   16384
#define NCAND 8

// Scratch (device globals: allocation-free)
__device__ __nv_bfloat16 g_abf[BDIM * NREF * DDIM];   // 1 MB bf16 gathered refs
__device__ __nv_bfloat16 g_sim[BDIM * NREF * EN];     // 16.8 MB bf16 sims
__device__ int   g_topk[BDIM * NREF * 4];
__device__ float g_accum[3];
__device__ unsigned g_done;

__constant__ int c_ST[3] = {2, 4, 6};   // SHARED_TEACHER
__constant__ int c_SS[3] = {1, 2, 3};   // SHARED_STUDENT

__device__ __forceinline__ void ins4(float x, int e, float* v, int* id) {
    if (x <= v[3]) return;
    v[3] = x; id[3] = e;
    #pragma unroll
    for (int j = 3; j >= 1; j--) {
        if (v[j] > v[j - 1]) {
            float tv = v[j]; v[j] = v[j - 1]; v[j - 1] = tv;
            int ti = id[j]; id[j] = id[j - 1]; id[j - 1] = ti;
        }
    }
}

__device__ __forceinline__ void ins8(float x, int e, float* v, int* id) {
    if (x <= v[7]) return;
    v[7] = x; id[7] = e;
    #pragma unroll
    for (int j = 7; j >= 1; j--) {
        if (v[j] > v[j - 1]) {
            float tv = v[j]; v[j] = v[j - 1]; v[j - 1] = tv;
            int ti = id[j]; id[j] = id[j - 1]; id[j - 1] = ti;
        }
    }
}

// ---------------------------------------------------------------------------
// K0: convert gathered REF rows only to bf16 (A side; 1 MB, trivial)
// ---------------------------------------------------------------------------
__global__ void __launch_bounds__(128)
k_convert(const float* __restrict__ teacher, const int* __restrict__ ref_perm) {
    const int id  = blockIdx.x;              // [0, BDIM*NREF)
    const int tid = threadIdx.x;
    int b = id >> 8, r = id & 255;
    const float* src = teacher + ((size_t)(b * VDIM) * PDIM + ref_perm[r]) * DDIM;
    __nv_bfloat16* dst = g_abf + (size_t)id * DDIM;

    float4 x0 = ((const float4*)src)[tid * 2];
    float4 x1 = ((const float4*)src)[tid * 2 + 1];
    __nv_bfloat162 h0, h1, h2, h3;
    h0.x = __float2bfloat16(x0.x); h0.y = __float2bfloat16(x0.y);
    h1.x = __float2bfloat16(x0.z); h1.y = __float2bfloat16(x0.w);
    h2.x = __float2bfloat16(x1.x); h2.y = __float2bfloat16(x1.y);
    h3.x = __float2bfloat16(x1.z); h3.y = __float2bfloat16(x1.w);
    uint4 pk;
    pk.x = *(uint32_t*)&h0; pk.y = *(uint32_t*)&h1;
    pk.z = *(uint32_t*)&h2; pk.w = *(uint32_t*)&h3;
    ((uint4*)dst)[tid] = pk;
}

// ---------------------------------------------------------------------------
// K1: bf16 GEMM, 256x128 CTA tile, B read DIRECTLY from f32 teacher via
//     cp.async + in-smem f32->bf16 convert + inline exact row norms.
//     512 threads, 16 warps (4x4), warp tile 64x32, 3-stage pipeline.
// ---------------------------------------------------------------------------
#define NKT   (DDIM / 32)        // 32 k-tiles
#define STAGES 3
#define AROWB 80                 // A bf16: 64 data + 16 pad
#define BF32ROWB 144             // B f32: 128 data + 16 pad
#define A_STAGE 20480            // 256 * 80
#define BF32_STAGE 18432         // 128 * 144
#define BBF_STAGE 10240          // 128 * 80
#define ABASE 0
#define BF32BASE (STAGES * A_STAGE)                  // 61440
#define BBFBASE (BF32BASE + STAGES * BF32_STAGE)     // 116736
#define GEMM_SMEM (BBFBASE + 2 * BBF_STAGE)          // 137216

__device__ __forceinline__ void cp_async16(uint32_t dst, const void* src) {
    asm volatile("cp.async.cg.shared.global [%0], [%1], 16;" :: "r"(dst), "l"(src));
}

__global__ void __launch_bounds__(512, 1)
k_gemm(const float* __restrict__ teacher) {
    extern __shared__ __align__(16) uint8_t smem[];
    __shared__ float s_inv[128];

    const int b     = blockIdx.z;
    const int ebase = blockIdx.x * 128;
    const int tid   = threadIdx.x;
    const int lane  = tid & 31;
    const int wid   = tid >> 5;          // 0..15
    const int wm    = (wid >> 2) * 64;
    const int wn    = (wid & 3) * 32;
    const uint32_t sbase = (uint32_t)__cvta_generic_to_shared(smem);

    const int v     = 2 * (ebase >> 12) + 1;      // EXTRA_FRAMES {1,3,5,7}
    const int pbase = ebase & (PDIM - 1);

    // A loaders: chunks cA = tid + s*512, s=0..1 (1024 chunks of 16B)
    const char* gA[2]; uint32_t sA[2];
    #pragma unroll
    for (int s = 0; s < 2; s++) {
        int c = tid + s * 512;
        int row = c >> 2, off = (c & 3) * 16;
        gA[s] = (const char*)(g_abf + ((size_t)(b * NREF + row)) * DDIM) + off;
        sA[s] = (uint32_t)(ABASE + row * AROWB + off);
    }
    // B f32 loaders: chunks cB = tid + s*512 (128 rows x 8 chunks of 16B)
    const char* gB[2]; uint32_t sB[2];
    #pragma unroll
    for (int s = 0; s < 2; s++) {
        int c = tid + s * 512;
        int row = c >> 3, off = (c & 7) * 16;
        gB[s] = (const char*)(teacher + ((size_t)(b * VDIM + v) * PDIM + pbase + row) * DDIM) + off;
        sB[s] = (uint32_t)(BF32BASE + row * BF32ROWB + off);
    }

    float acc[4][4][4];
    #pragma unroll
    for (int i = 0; i < 4; i++)
        #pragma unroll
        for (int j = 0; j < 4; j++)
            #pragma unroll
            for (int k = 0; k < 4; k++) acc[i][j][k] = 0.f;

    // ldmatrix lane addressing (byte offsets)
    const int xr = (lane & 7) + ((lane >> 3) & 1) * 8;
    const int xk = (lane >> 4) * 16;
    uint32_t a_off[4], b_off[2];
    #pragma unroll
    for (int mi = 0; mi < 4; mi++)
        a_off[mi] = (uint32_t)(ABASE + (wm + mi * 16 + xr) * AROWB + xk);
    #pragma unroll
    for (int nj = 0; nj < 2; nj++)
        b_off[nj] = (uint32_t)(BBFBASE + (wn + nj * 16 + xr) * AROWB + xk);

    // convert-phase indices: 4 threads per B row
    const int crow = tid >> 2;
    const int cseg = tid & 3;
    float ssq = 0.f;

    // prologue: stages 0..1
    #pragma unroll
    for (int s = 0; s < STAGES - 1; s++) {
        #pragma unroll
        for (int q = 0; q < 2; q++) {
            cp_async16(sbase + s * A_STAGE + sA[q], gA[q] + s * 64);
            cp_async16(sbase + BF32BASE - BF32BASE + s * BF32_STAGE + sB[q], gB[q] + s * 128);
        }
        asm volatile("cp.async.commit_group;");
    }

    for (int kt = 0; kt < NKT; kt++) {
        asm volatile("cp.async.wait_group %0;" :: "n"(STAGES - 2));
        __syncthreads();

        int wst = kt + STAGES - 1;
        if (wst < NKT) {
            int st = wst % STAGES;
            #pragma unroll
            for (int q = 0; q < 2; q++) {
                cp_async16(sbase + st * A_STAGE + sA[q], gA[q] + wst * 64);
                cp_async16(sbase + st * BF32_STAGE + sB[q], gB[q] + wst * 128);
            }
        }
        asm volatile("cp.async.commit_group;");

        const int stg = kt % STAGES;
        // convert: read 8 f32 from B f32 stage, write 8 bf16, accumulate ssq
        {
            const float* fsrc = (const float*)(smem + BF32BASE + stg * BF32_STAGE
                                               + crow * BF32ROWB + cseg * 32);
            float4 x0 = ((const float4*)fsrc)[0];
            float4 x1 = ((const float4*)fsrc)[1];
            ssq += x0.x * x0.x + x0.y * x0.y + x0.z * x0.z + x0.w * x0.w
                 + x1.x * x1.x + x1.y * x1.y + x1.z * x1.z + x1.w * x1.w;
            __nv_bfloat162 h0, h1, h2, h3;
            h0.x = __float2bfloat16(x0.x); h0.y = __float2bfloat16(x0.y);
            h1.x = __float2bfloat16(x0.z); h1.y = __float2bfloat16(x0.w);
            h2.x = __float2bfloat16(x1.x); h2.y = __float2bfloat16(x1.y);
            h3.x = __float2bfloat16(x1.z); h3.y = __float2bfloat16(x1.w);
            uint4 pk;
            pk.x = *(uint32_t*)&h0; pk.y = *(uint32_t*)&h1;
            pk.z = *(uint32_t*)&h2; pk.w = *(uint32_t*)&h3;
            *(uint4*)(smem + BBFBASE + (kt & 1) * BBF_STAGE + crow * AROWB + cseg * 16) = pk;
        }
        __syncthreads();

        const uint32_t astg = (uint32_t)(stg * A_STAGE);
        const uint32_t bbuf = (uint32_t)((kt & 1) * BBF_STAGE);
        #pragma unroll
        for (int ks = 0; ks < 64; ks += 32) {
            uint32_t af[4][4], bf[2][4];
            #pragma unroll
            for (int mi = 0; mi < 4; mi++) {
                asm volatile("ldmatrix.sync.aligned.m8n8.x4.shared.b16 {%0,%1,%2,%3}, [%4];"
                    : "=r"(af[mi][0]), "=r"(af[mi][1]), "=r"(af[mi][2]), "=r"(af[mi][3])
                    : "r"(sbase + astg + a_off[mi] + ks));
            }
            #pragma unroll
            for (int nj = 0; nj < 2; nj++) {
                asm volatile("ldmatrix.sync.aligned.m8n8.x4.shared.b16 {%0,%1,%2,%3}, [%4];"
                    : "=r"(bf[nj][0]), "=r"(bf[nj][1]), "=r"(bf[nj][2]), "=r"(bf[nj][3])
                    : "r"(sbase + bbuf + b_off[nj] + ks));
            }
            #pragma unroll
            for (int mi = 0; mi < 4; mi++) {
                #pragma unroll
                for (int nj = 0; nj < 4; nj++) {
                    uint32_t bb0 = bf[nj >> 1][nj & 1];
                    uint32_t bb1 = bf[nj >> 1][(nj & 1) + 2];
                    asm volatile(
                        "mma.sync.aligned.m16n8k16.row.col.f32.bf16.bf16.f32 "
                        "{%0,%1,%2,%3}, {%4,%5,%6,%7}, {%8,%9}, {%0,%1,%2,%3};"
                        : "+f"(acc[mi][nj][0]), "+f"(acc[mi][nj][1]),
                          "+f"(acc[mi][nj][2]), "+f"(acc[mi][nj][3])
                        : "r"(af[mi][0]), "r"(af[mi][1]), "r"(af[mi][2]), "r"(af[mi][3]),
                          "r"(bb0), "r"(bb1));
                }
            }
        }
    }

    // exact B-row inverse norms: 4 threads per row (consecutive lanes)
    ssq += __shfl_xor_sync(0xffffffffu, ssq, 1);
    ssq += __shfl_xor_sync(0xffffffffu, ssq, 2);
    if ((tid & 3) == 0) s_inv[crow] = 1.0f / fmaxf(sqrtf(ssq), 1e-12f);
    __syncthreads();

    // epilogue: scale by inv_norm[e], write bf16 sims (4B packed stores)
    #pragma unroll
    for (int mi = 0; mi < 4; mi++) {
        int r = wm + mi * 16 + (lane >> 2);
        __nv_bfloat16* orow = g_sim + ((size_t)(b * NREF + r)) * EN + ebase;
        #pragma unroll
        for (int nj = 0; nj < 4; nj++) {
            int c = wn + nj * 8 + (lane & 3) * 2;
            __nv_bfloat162 h0, h1;
            h0.x = __float2bfloat16(acc[mi][nj][0] * s_inv[c]);
            h0.y = __float2bfloat16(acc[mi][nj][1] * s_inv[c + 1]);
            h1.x = __float2bfloat16(acc[mi][nj][2] * s_inv[c]);
            h1.y = __float2bfloat16(acc[mi][nj][3] * s_inv[c + 1]);
            *(uint32_t*)(orow + c)          = *(uint32_t*)&h0;
            *(uint32_t*)(orow + 8 * EN + c) = *(uint32_t*)&h1;
        }
    }
}

// ---------------------------------------------------------------------------
// K2: per (b,r): top-8 candidates from bf16 sims (vectorized 16B loads),
//     then exact fp32 re-rank -> exact top-4 indices.
// ---------------------------------------------------------------------------
__global__ void __launch_bounds__(256)
k_select(const float* __restrict__ teacher, const int* __restrict__ ref_perm) {
    int r = blockIdx.x, b = blockIdx.y, tid = threadIdx.x;
    int w = tid >> 5, lane = tid & 31;
    const __nv_bfloat16* row = g_sim + ((size_t)(b * NREF + r)) * EN;

    if (r == 0 && b == 0 && tid < 3) g_accum[tid] = 0.f;

    float v[4] = {-3.4e38f, -3.4e38f, -3.4e38f, -3.4e38f};
    int id[4] = {0, 0, 0, 0};
    #pragma unroll
    for (int k = 0; k < 8; k++) {
        int base = (k * 256 + tid) * 8;
        uint4 pk = *(const uint4*)(row + base);
        uint32_t uu[4] = {pk.x, pk.y, pk.z, pk.w};
        #pragma unroll
        for (int q = 0; q < 4; q++) {
            __nv_bfloat162 h = *(__nv_bfloat162*)&uu[q];
            ins4(__bfloat162float(h.x), base + q * 2,     v, id);
            ins4(__bfloat162float(h.y), base + q * 2 + 1, v, id);
        }
    }

    __shared__ float sv[1024];
    __shared__ int   si[1024];
    __shared__ int   s_cand[NCAND];
    __shared__ float s_sim[NCAND];
    __shared__ int   s_e[NCAND];

    #pragma unroll
    for (int j = 0; j < 4; j++) { sv[tid * 4 + j] = v[j]; si[tid * 4 + j] = id[j]; }
    __syncthreads();

    if (tid < 32) {
        float v2[4] = {-3.4e38f, -3.4e38f, -3.4e38f, -3.4e38f};
        int id2[4] = {0, 0, 0, 0};
        for (int t = tid * 32; t < tid * 32 + 32; t++) ins4(sv[t], si[t], v2, id2);
        __syncwarp();
        #pragma unroll
        for (int j = 0; j < 4; j++) { sv[tid * 4 + j] = v2[j]; si[tid * 4 + j] = id2[j]; }
        __syncwarp();
        if (tid == 0) {
            float v3[8]; int id3[8];
            #pragma unroll
            for (int j = 0; j < 8; j++) { v3[j] = -3.4e38f; id3[j] = 0; }
            for (int t = 0; t < 128; t++) ins8(sv[t], si[t], v3, id3);
            #pragma unroll
            for (int j = 0; j < 8; j++) s_cand[j] = id3[j];
        }
    }
    __syncthreads();

    int e = s_cand[w];
    int vv = 2 * (e >> 12) + 1, p = e & (PDIM - 1);
    const float* er = teacher + ((size_t)(b * VDIM + vv) * PDIM + p) * DDIM;
    const float* rr = teacher + ((size_t)(b * VDIM) * PDIM + ref_perm[r]) * DDIM;

    float dot = 0.f, ss = 0.f;
    #pragma unroll
    for (int j = 0; j < 8; j++) {
        int idx = lane * 4 + j * 128;
        float4 x = *(const float4*)(er + idx);
        float4 y = *(const float4*)(rr + idx);
        dot += x.x * y.x + x.y * y.y + x.z * y.z + x.w * y.w;
        ss  += x.x * x.x + x.y * x.y + x.z * x.z + x.w * x.w;
    }
    #pragma unroll
    for (int o = 16; o; o >>= 1) {
        dot += __shfl_xor_sync(0xffffffffu, dot, o);
        ss  += __shfl_xor_sync(0xffffffffu, ss, o);
    }
    if (lane == 0) {
        s_sim[w] = dot / fmaxf(sqrtf(ss), 1e-12f);
        s_e[w] = e;
    }
    __syncthreads();

    if (tid == 0) {
        bool used[NCAND] = {false, false, false, false, false, false, false, false};
        #pragma unroll
        for (int j = 0; j < 4; j++) {
            int best = -1;
            float bvv = -3.4e38f; int be = 0x7fffffff;
            for (int t = 0; t < NCAND; t++) {
                if (used[t]) continue;
                if (s_sim[t] > bvv || (s_sim[t] == bvv && s_e[t] < be)) {
                    bvv = s_sim[t]; be = s_e[t]; best = t;
                }
            }
            used[best] = true;
            g_topk[(b * NREF + r) * 4 + j] = s_e[best];
        }
    }
}

// ---------------------------------------------------------------------------
// K3: KL + smooth-L1 losses, 64 threads per row-pair, fast-math exp/log;
//     last-arriving block writes the final scalar.
// ---------------------------------------------------------------------------
__global__ void __launch_bounds__(256)
k_loss(const float* __restrict__ teacher, const float* __restrict__ student,
       const int* __restrict__ ref_perm, const int* __restrict__ shared_perm,
       float* __restrict__ out) {
    __shared__ float sacc[3];
    __shared__ float r0[4][2], r1[4][2];
    int tid = threadIdx.x;
    if (tid < 3) sacc[tid] = 0.f;

    int grp  = tid >> 6;
    int sub  = tid & 63;
    int w2   = (tid >> 5) & 1;
    int lane = tid & 31;
    int w    = blockIdx.x * 4 + grp;

    const float *pa, *pb, *pc, *pd;
    int target;
    if (w < 1536) {
        target = 0;
        int i = w / 512, rem = w & 511;
        int b = rem >> 8, r = rem & 255;
        int rp = ref_perm[r], sp = shared_perm[r];
        pa = teacher + ((size_t)(b * VDIM) * PDIM + rp) * DDIM;
        pb = teacher + ((size_t)(b * VDIM + c_ST[i]) * PDIM + sp) * DDIM;
        pc = student + ((size_t)(b * 4) * PDIM + rp) * DDIM;
        pd = student + ((size_t)(b * 4 + c_SS[i]) * PDIM + sp) * DDIM;
    } else if (w < 3584) {
        target = 1;
        int t = w - 1536;
        int b = t >> 10, rem = t & 1023;
        int r = rem >> 2, k = rem & 3;
        int rp = ref_perm[r];
        int e = g_topk[((b << 8) + r) * 4 + k];
        int v = 2 * (e >> 12) + 1, p = e & (PDIM - 1);
        pa = teacher + ((size_t)(b * VDIM) * PDIM + rp) * DDIM;
        pc = student + ((size_t)(b * 4) * PDIM + rp) * DDIM;
        pb = pd = teacher + ((size_t)(b * VDIM + v) * PDIM + p) * DDIM;
    } else {
        target = 2;
        int t = w - 3584;
        int i = t >> 11, rem = t & 2047;
        int b = rem >> 10, r = (rem >> 2) & 255, k = rem & 3;
        int sp = shared_perm[r];
        int e = g_topk[((b << 8) + r) * 4 + k];
        int v = 2 * (e >> 12) + 1, p = e & (PDIM - 1);
        pa = teacher + ((size_t)(b * VDIM + c_ST[i]) * PDIM + sp) * DDIM;
        pc = student + ((size_t)(b * 4 + c_SS[i]) * PDIM + sp) * DDIM;
        pb = pd = teacher + ((size_t)(b * VDIM + v) * PDIM + p) * DDIM;
    }

    float dt[16], ds[16];
    bool same = (pb == pd);
    #pragma unroll
    for (int j = 0; j < 4; j++) {
        int idx = sub * 4 + j * 256;
        float4 A  = *(const float4*)(pa + idx);
        float4 Bv = *(const float4*)(pb + idx);
        float4 C  = *(const float4*)(pc + idx);
        float4 Dv = same ? Bv : *(const float4*)(pd + idx);
        dt[4 * j + 0] = A.x - Bv.x; dt[4 * j + 1] = A.y - Bv.y;
        dt[4 * j + 2] = A.z - Bv.z; dt[4 * j + 3] = A.w - Bv.w;
        ds[4 * j + 0] = C.x - Dv.x; ds[4 * j + 1] = C.y - Dv.y;
        ds[4 * j + 2] = C.z - Dv.z; ds[4 * j + 3] = C.w - Dv.w;
    }

    float mt = -3.4e38f, ms = -3.4e38f;
    #pragma unroll
    for (int i = 0; i < 16; i++) { mt = fmaxf(mt, dt[i]); ms = fmaxf(ms, ds[i]); }
    #pragma unroll
    for (int o = 16; o; o >>= 1) {
        mt = fmaxf(mt, __shfl_xor_sync(0xffffffffu, mt, o));
        ms = fmaxf(ms, __shfl_xor_sync(0xffffffffu, ms, o));
    }
    if (lane == 0) { r0[grp][w2] = mt; r1[grp][w2] = ms; }
    __syncthreads();
    mt = fmaxf(r0[grp][0], r0[grp][1]);
    ms = fmaxf(r1[grp][0], r1[grp][1]);

    float st = 0.f, ssum = 0.f;
    #pragma unroll
    for (int i = 0; i < 16; i++) { st += __expf(dt[i] - mt); ssum += __expf(ds[i] - ms); }
    #pragma unroll
    for (int o = 16; o; o >>= 1) {
        st   += __shfl_xor_sync(0xffffffffu, st, o);
        ssum += __shfl_xor_sync(0xffffffffu, ssum, o);
    }
    __syncthreads();
    if (lane == 0) { r0[grp][w2] = st; r1[grp][w2] = ssum; }
    __syncthreads();
    float lset = mt + __logf(r0[grp][0] + r0[grp][1]);
    float lses = ms + __logf(r1[grp][0] + r1[grp][1]);

    float acc = 0.f;
    #pragma unroll
    for (int i = 0; i < 16; i++) acc += __expf(dt[i] - lset) * (dt[i] - ds[i]);
    #pragma unroll
    for (int o = 16; o; o >>= 1) acc += __shfl_xor_sync(0xffffffffu, acc, o);
    __syncthreads();
    if (lane == 0) r0[grp][w2] = acc;
    __syncthreads();

    if (sub == 0) {
        float kl = (r0[grp][0] + r0[grp][1]) - lset + lses;
        float ax = fabsf(kl);
        float sl = (ax < 0.5f) ? kl * kl : (ax - 0.25f);   // smooth_l1, beta=0.5
        atomicAdd(&sacc[target], sl);
    }
    __syncthreads();
    if (tid < 3) atomicAdd(&g_accum[tid], sacc[tid]);

    // last-arriving block folds the final combine
    __syncthreads();
    if (tid == 0) {
        __threadfence();
        unsigned t = atomicAdd(&g_done, 1);
        if (t == gridDim.x - 1) {
            __threadfence();
            out[0] = g_accum[0] * (1.0f / 1536.0f)
                   + g_accum[1] * (1.0f / 2048.0f)
                   + g_accum[2] * (1.0f / 6144.0f);
            g_done = 0;
        }
    }
}

// ---------------------------------------------------------------------------
extern "C" void kernel_launch(void* const* d_in, const int* in_sizes, int n_in,
                              void* d_out, int out_size) {
    const float* teacher     = (const float*)d_in[0];
    const float* student     = (const float*)d_in[1];
    const int*   ref_perm    = (const int*)d_in[2];
    const int*   shared_perm = (const int*)d_in[3];
    float* out = (float*)d_out;

    cudaFuncSetAttribute(k_gemm, cudaFuncAttributeMaxDynamicSharedMemorySize, GEMM_SMEM);

    k_convert<<<BDIM * NREF, 128>>>(teacher, ref_perm);
    k_gemm<<<dim3(EN / 128, 1, BDIM), 512, GEMM_SMEM>>>(teacher);
    k_select<<<dim3(NREF, BDIM), 256>>>(teacher, ref_perm);
    k_loss<<<9728 / 4, 256>>>(teacher, student, ref_perm, shared_perm, out);
}

// round 13
// speedup vs baseline: 1.0670x; 1.0007x over previous
#include <cuda_runtime.h>
#include <cuda_bf16.h>
#include <cstdint>

// Problem constants
#define BDIM 2
#define VDIM 8
#define PDIM 4096
#define DDIM 1024
#define NREF 256
#define EN   16384
#define NCAND 8

// Scratch (device globals: allocation-free)
__device__ __nv_bfloat16 g_abf[BDIM * NREF * DDIM];   // 1 MB bf16 gathered refs
__device__ __nv_bfloat16 g_sim[BDIM * NREF * EN];     // 16.8 MB bf16 sims
__device__ int   g_topk[BDIM * NREF * 4];
__device__ float g_accum[3];
__device__ unsigned g_done;

__constant__ int c_ST[3] = {2, 4, 6};   // SHARED_TEACHER
__constant__ int c_SS[3] = {1, 2, 3};   // SHARED_STUDENT

__device__ __forceinline__ void ins4(float x, int e, float* v, int* id) {
    if (x <= v[3]) return;
    v[3] = x; id[3] = e;
    #pragma unroll
    for (int j = 3; j >= 1; j--) {
        if (v[j] > v[j - 1]) {
            float tv = v[j]; v[j] = v[j - 1]; v[j - 1] = tv;
            int ti = id[j]; id[j] = id[j - 1]; id[j - 1] = ti;
        }
    }
}

__device__ __forceinline__ void ins8(float x, int e, float* v, int* id) {
    if (x <= v[7]) return;
    v[7] = x; id[7] = e;
    #pragma unroll
    for (int j = 7; j >= 1; j--) {
        if (v[j] > v[j - 1]) {
            float tv = v[j]; v[j] = v[j - 1]; v[j - 1] = tv;
            int ti = id[j]; id[j] = id[j - 1]; id[j - 1] = ti;
        }
    }
}

// ---------------------------------------------------------------------------
// K0: convert gathered REF rows only to bf16 (A side; 1 MB, trivial)
// ---------------------------------------------------------------------------
__global__ void __launch_bounds__(128)
k_convert(const float* __restrict__ teacher, const int* __restrict__ ref_perm) {
    const int id  = blockIdx.x;              // [0, BDIM*NREF)
    const int tid = threadIdx.x;
    int b = id >> 8, r = id & 255;
    const float* src = teacher + ((size_t)(b * VDIM) * PDIM + ref_perm[r]) * DDIM;
    __nv_bfloat16* dst = g_abf + (size_t)id * DDIM;

    float4 x0 = ((const float4*)src)[tid * 2];
    float4 x1 = ((const float4*)src)[tid * 2 + 1];
    __nv_bfloat162 h0, h1, h2, h3;
    h0.x = __float2bfloat16(x0.x); h0.y = __float2bfloat16(x0.y);
    h1.x = __float2bfloat16(x0.z); h1.y = __float2bfloat16(x0.w);
    h2.x = __float2bfloat16(x1.x); h2.y = __float2bfloat16(x1.y);
    h3.x = __float2bfloat16(x1.z); h3.y = __float2bfloat16(x1.w);
    uint4 pk;
    pk.x = *(uint32_t*)&h0; pk.y = *(uint32_t*)&h1;
    pk.z = *(uint32_t*)&h2; pk.w = *(uint32_t*)&h3;
    ((uint4*)dst)[tid] = pk;
}

// ---------------------------------------------------------------------------
// K1: bf16 GEMM, 256x128 CTA tile, B read DIRECTLY from f32 teacher via
//     cp.async + in-smem f32->bf16 convert + inline exact row norms.
//     512 threads, 16 warps (4x4), warp tile 64x32, 3-stage pipeline.
// ---------------------------------------------------------------------------
#define NKT   (DDIM / 32)        // 32 k-tiles
#define STAGES 3
#define AROWB 80                 // A bf16: 64 data + 16 pad
#define BF32ROWB 144             // B f32: 128 data + 16 pad
#define A_STAGE 20480            // 256 * 80
#define BF32_STAGE 18432         // 128 * 144
#define BBF_STAGE 10240          // 128 * 80
#define ABASE 0
#define BF32BASE (STAGES * A_STAGE)                  // 61440
#define BBFBASE (BF32BASE + STAGES * BF32_STAGE)     // 116736
#define GEMM_SMEM (BBFBASE + 2 * BBF_STAGE)          // 137216

__device__ __forceinline__ void cp_async16(uint32_t dst, const void* src) {
    asm volatile("cp.async.cg.shared.global [%0], [%1], 16;" :: "r"(dst), "l"(src));
}

__global__ void __launch_bounds__(512, 1)
k_gemm(const float* __restrict__ teacher) {
    extern __shared__ __align__(16) uint8_t smem[];
    __shared__ float s_inv[128];

    const int b     = blockIdx.z;
    const int ebase = blockIdx.x * 128;
    const int tid   = threadIdx.x;
    const int lane  = tid & 31;
    const int wid   = tid >> 5;          // 0..15
    const int wm    = (wid >> 2) * 64;
    const int wn    = (wid & 3) * 32;
    const uint32_t sbase = (uint32_t)__cvta_generic_to_shared(smem);

    const int v     = 2 * (ebase >> 12) + 1;      // EXTRA_FRAMES {1,3,5,7}
    const int pbase = ebase & (PDIM - 1);

    // A loaders: chunks cA = tid + s*512, s=0..1 (1024 chunks of 16B)
    const char* gA[2]; uint32_t sA[2];
    #pragma unroll
    for (int s = 0; s < 2; s++) {
        int c = tid + s * 512;
        int row = c >> 2, off = (c & 3) * 16;
        gA[s] = (const char*)(g_abf + ((size_t)(b * NREF + row)) * DDIM) + off;
        sA[s] = (uint32_t)(ABASE + row * AROWB + off);
    }
    // B f32 loaders: chunks cB = tid + s*512 (128 rows x 8 chunks of 16B)
    const char* gB[2]; uint32_t sB[2];
    #pragma unroll
    for (int s = 0; s < 2; s++) {
        int c = tid + s * 512;
        int row = c >> 3, off = (c & 7) * 16;
        gB[s] = (const char*)(teacher + ((size_t)(b * VDIM + v) * PDIM + pbase + row) * DDIM) + off;
        sB[s] = (uint32_t)(BF32BASE + row * BF32ROWB + off);
    }

    float acc[4][4][4];
    #pragma unroll
    for (int i = 0; i < 4; i++)
        #pragma unroll
        for (int j = 0; j < 4; j++)
            #pragma unroll
            for (int k = 0; k < 4; k++) acc[i][j][k] = 0.f;

    // ldmatrix lane addressing (byte offsets)
    const int xr = (lane & 7) + ((lane >> 3) & 1) * 8;
    const int xk = (lane >> 4) * 16;
    uint32_t a_off[4], b_off[2];
    #pragma unroll
    for (int mi = 0; mi < 4; mi++)
        a_off[mi] = (uint32_t)(ABASE + (wm + mi * 16 + xr) * AROWB + xk);
    #pragma unroll
    for (int nj = 0; nj < 2; nj++)
        b_off[nj] = (uint32_t)(BBFBASE + (wn + nj * 16 + xr) * AROWB + xk);

    // convert-phase indices: 4 threads per B row
    const int crow = tid >> 2;
    const int cseg = tid & 3;
    float ssq = 0.f;

    // prologue: stages 0..1
    #pragma unroll
    for (int s = 0; s < STAGES - 1; s++) {
        #pragma unroll
        for (int q = 0; q < 2; q++) {
            cp_async16(sbase + s * A_STAGE + sA[q], gA[q] + s * 64);
            cp_async16(sbase + BF32BASE - BF32BASE + s * BF32_STAGE + sB[q], gB[q] + s * 128);
        }
        asm volatile("cp.async.commit_group;");
    }

    for (int kt = 0; kt < NKT; kt++) {
        asm volatile("cp.async.wait_group %0;" :: "n"(STAGES - 2));
        __syncthreads();

        int wst = kt + STAGES - 1;
        if (wst < NKT) {
            int st = wst % STAGES;
            #pragma unroll
            for (int q = 0; q < 2; q++) {
                cp_async16(sbase + st * A_STAGE + sA[q], gA[q] + wst * 64);
                cp_async16(sbase + st * BF32_STAGE + sB[q], gB[q] + wst * 128);
            }
        }
        asm volatile("cp.async.commit_group;");

        const int stg = kt % STAGES;
        // convert: read 8 f32 from B f32 stage, write 8 bf16, accumulate ssq
        {
            const float* fsrc = (const float*)(smem + BF32BASE + stg * BF32_STAGE
                                               + crow * BF32ROWB + cseg * 32);
            float4 x0 = ((const float4*)fsrc)[0];
            float4 x1 = ((const float4*)fsrc)[1];
            ssq += x0.x * x0.x + x0.y * x0.y + x0.z * x0.z + x0.w * x0.w
                 + x1.x * x1.x + x1.y * x1.y + x1.z * x1.z + x1.w * x1.w;
            __nv_bfloat162 h0, h1, h2, h3;
            h0.x = __float2bfloat16(x0.x); h0.y = __float2bfloat16(x0.y);
            h1.x = __float2bfloat16(x0.z); h1.y = __float2bfloat16(x0.w);
            h2.x = __float2bfloat16(x1.x); h2.y = __float2bfloat16(x1.y);
            h3.x = __float2bfloat16(x1.z); h3.y = __float2bfloat16(x1.w);
            uint4 pk;
            pk.x = *(uint32_t*)&h0; pk.y = *(uint32_t*)&h1;
            pk.z = *(uint32_t*)&h2; pk.w = *(uint32_t*)&h3;
            *(uint4*)(smem + BBFBASE + (kt & 1) * BBF_STAGE + crow * AROWB + cseg * 16) = pk;
        }
        __syncthreads();

        const uint32_t astg = (uint32_t)(stg * A_STAGE);
        const uint32_t bbuf = (uint32_t)((kt & 1) * BBF_STAGE);
        #pragma unroll
        for (int ks = 0; ks < 64; ks += 32) {
            uint32_t af[4][4], bf[2][4];
            #pragma unroll
            for (int mi = 0; mi < 4; mi++) {
                asm volatile("ldmatrix.sync.aligned.m8n8.x4.shared.b16 {%0,%1,%2,%3}, [%4];"
                    : "=r"(af[mi][0]), "=r"(af[mi][1]), "=r"(af[mi][2]), "=r"(af[mi][3])
                    : "r"(sbase + astg + a_off[mi] + ks));
            }
            #pragma unroll
            for (int nj = 0; nj < 2; nj++) {
                asm volatile("ldmatrix.sync.aligned.m8n8.x4.shared.b16 {%0,%1,%2,%3}, [%4];"
                    : "=r"(bf[nj][0]), "=r"(bf[nj][1]), "=r"(bf[nj][2]), "=r"(bf[nj][3])
                    : "r"(sbase + bbuf + b_off[nj] + ks));
            }
            #pragma unroll
            for (int mi = 0; mi < 4; mi++) {
                #pragma unroll
                for (int nj = 0; nj < 4; nj++) {
                    uint32_t bb0 = bf[nj >> 1][nj & 1];
                    uint32_t bb1 = bf[nj >> 1][(nj & 1) + 2];
                    asm volatile(
                        "mma.sync.aligned.m16n8k16.row.col.f32.bf16.bf16.f32 "
                        "{%0,%1,%2,%3}, {%4,%5,%6,%7}, {%8,%9}, {%0,%1,%2,%3};"
                        : "+f"(acc[mi][nj][0]), "+f"(acc[mi][nj][1]),
                          "+f"(acc[mi][nj][2]), "+f"(acc[mi][nj][3])
                        : "r"(af[mi][0]), "r"(af[mi][1]), "r"(af[mi][2]), "r"(af[mi][3]),
                          "r"(bb0), "r"(bb1));
                }
            }
        }
    }

    // exact B-row inverse norms: 4 threads per row (consecutive lanes)
    ssq += __shfl_xor_sync(0xffffffffu, ssq, 1);
    ssq += __shfl_xor_sync(0xffffffffu, ssq, 2);
    if ((tid & 3) == 0) s_inv[crow] = 1.0f / fmaxf(sqrtf(ssq), 1e-12f);
    __syncthreads();

    // epilogue: scale by inv_norm[e], write bf16 sims (4B packed stores)
    #pragma unroll
    for (int mi = 0; mi < 4; mi++) {
        int r = wm + mi * 16 + (lane >> 2);
        __nv_bfloat16* orow = g_sim + ((size_t)(b * NREF + r)) * EN + ebase;
        #pragma unroll
        for (int nj = 0; nj < 4; nj++) {
            int c = wn + nj * 8 + (lane & 3) * 2;
            __nv_bfloat162 h0, h1;
            h0.x = __float2bfloat16(acc[mi][nj][0] * s_inv[c]);
            h0.y = __float2bfloat16(acc[mi][nj][1] * s_inv[c + 1]);
            h1.x = __float2bfloat16(acc[mi][nj][2] * s_inv[c]);
            h1.y = __float2bfloat16(acc[mi][nj][3] * s_inv[c + 1]);
            *(uint32_t*)(orow + c)          = *(uint32_t*)&h0;
            *(uint32_t*)(orow + 8 * EN + c) = *(uint32_t*)&h1;
        }
    }
}

// ---------------------------------------------------------------------------
// K2: per (b,r): top-8 candidates from bf16 sims (vectorized 16B loads),
//     then exact fp32 re-rank -> exact top-4 indices.
// ---------------------------------------------------------------------------
__global__ void __launch_bounds__(256)
k_select(const float* __restrict__ teacher, const int* __restrict__ ref_perm) {
    int r = blockIdx.x, b = blockIdx.y, tid = threadIdx.x;
    int w = tid >> 5, lane = tid & 31;
    const __nv_bfloat16* row = g_sim + ((size_t)(b * NREF + r)) * EN;

    if (r == 0 && b == 0 && tid < 3) g_accum[tid] = 0.f;

    float v[4] = {-3.4e38f, -3.4e38f, -3.4e38f, -3.4e38f};
    int id[4] = {0, 0, 0, 0};
    #pragma unroll
    for (int k = 0; k < 8; k++) {
        int base = (k * 256 + tid) * 8;
        uint4 pk = *(const uint4*)(row + base);
        uint32_t uu[4] = {pk.x, pk.y, pk.z, pk.w};
        #pragma unroll
        for (int q = 0; q < 4; q++) {
            __nv_bfloat162 h = *(__nv_bfloat162*)&uu[q];
            ins4(__bfloat162float(h.x), base + q * 2,     v, id);
            ins4(__bfloat162float(h.y), base + q * 2 + 1, v, id);
        }
    }

    __shared__ float sv[1024];
    __shared__ int   si[1024];
    __shared__ int   s_cand[NCAND];
    __shared__ float s_sim[NCAND];
    __shared__ int   s_e[NCAND];

    #pragma unroll
    for (int j = 0; j < 4; j++) { sv[tid * 4 + j] = v[j]; si[tid * 4 + j] = id[j]; }
    __syncthreads();

    if (tid < 32) {
        float v2[4] = {-3.4e38f, -3.4e38f, -3.4e38f, -3.4e38f};
        int id2[4] = {0, 0, 0, 0};
        for (int t = tid * 32; t < tid * 32 + 32; t++) ins4(sv[t], si[t], v2, id2);
        __syncwarp();
        #pragma unroll
        for (int j = 0; j < 4; j++) { sv[tid * 4 + j] = v2[j]; si[tid * 4 + j] = id2[j]; }
        __syncwarp();
        if (tid == 0) {
            float v3[8]; int id3[8];
            #pragma unroll
            for (int j = 0; j < 8; j++) { v3[j] = -3.4e38f; id3[j] = 0; }
            for (int t = 0; t < 128; t++) ins8(sv[t], si[t], v3, id3);
            #pragma unroll
            for (int j = 0; j < 8; j++) s_cand[j] = id3[j];
        }
    }
    __syncthreads();

    int e = s_cand[w];
    int vv = 2 * (e >> 12) + 1, p = e & (PDIM - 1);
    const float* er = teacher + ((size_t)(b * VDIM + vv) * PDIM + p) * DDIM;
    const float* rr = teacher + ((size_t)(b * VDIM) * PDIM + ref_perm[r]) * DDIM;

    float dot = 0.f, ss = 0.f;
    #pragma unroll
    for (int j = 0; j < 8; j++) {
        int idx = lane * 4 + j * 128;
        float4 x = *(const float4*)(er + idx);
        float4 y = *(const float4*)(rr + idx);
        dot += x.x * y.x + x.y * y.y + x.z * y.z + x.w * y.w;
        ss  += x.x * x.x + x.y * x.y + x.z * x.z + x.w * x.w;
    }
    #pragma unroll
    for (int o = 16; o; o >>= 1) {
        dot += __shfl_xor_sync(0xffffffffu, dot, o);
        ss  += __shfl_xor_sync(0xffffffffu, ss, o);
    }
    if (lane == 0) {
        s_sim[w] = dot / fmaxf(sqrtf(ss), 1e-12f);
        s_e[w] = e;
    }
    __syncthreads();

    if (tid == 0) {
        bool used[NCAND] = {false, false, false, false, false, false, false, false};
        #pragma unroll
        for (int j = 0; j < 4; j++) {
            int best = -1;
            float bvv = -3.4e38f; int be = 0x7fffffff;
            for (int t = 0; t < NCAND; t++) {
                if (used[t]) continue;
                if (s_sim[t] > bvv || (s_sim[t] == bvv && s_e[t] < be)) {
                    bvv = s_sim[t]; be = s_e[t]; best = t;
                }
            }
            used[best] = true;
            g_topk[(b * NREF + r) * 4 + j] = s_e[best];
        }
    }
}

// ---------------------------------------------------------------------------
// K3: KL + smooth-L1 losses, 64 threads per row-pair, fast-math exp/log;
//     last-arriving block writes the final scalar.
// ---------------------------------------------------------------------------
__global__ void __launch_bounds__(256)
k_loss(const float* __restrict__ teacher, const float* __restrict__ student,
       const int* __restrict__ ref_perm, const int* __restrict__ shared_perm,
       float* __restrict__ out) {
    __shared__ float sacc[3];
    __shared__ float r0[4][2], r1[4][2];
    int tid = threadIdx.x;
    if (tid < 3) sacc[tid] = 0.f;

    int grp  = tid >> 6;
    int sub  = tid & 63;
    int w2   = (tid >> 5) & 1;
    int lane = tid & 31;
    int w    = blockIdx.x * 4 + grp;

    const float *pa, *pb, *pc, *pd;
    int target;
    if (w < 1536) {
        target = 0;
        int i = w / 512, rem = w & 511;
        int b = rem >> 8, r = rem & 255;
        int rp = ref_perm[r], sp = shared_perm[r];
        pa = teacher + ((size_t)(b * VDIM) * PDIM + rp) * DDIM;
        pb = teacher + ((size_t)(b * VDIM + c_ST[i]) * PDIM + sp) * DDIM;
        pc = student + ((size_t)(b * 4) * PDIM + rp) * DDIM;
        pd = student + ((size_t)(b * 4 + c_SS[i]) * PDIM + sp) * DDIM;
    } else if (w < 3584) {
        target = 1;
        int t = w - 1536;
        int b = t >> 10, rem = t & 1023;
        int r = rem >> 2, k = rem & 3;
        int rp = ref_perm[r];
        int e = g_topk[((b << 8) + r) * 4 + k];
        int v = 2 * (e >> 12) + 1, p = e & (PDIM - 1);
        pa = teacher + ((size_t)(b * VDIM) * PDIM + rp) * DDIM;
        pc = student + ((size_t)(b * 4) * PDIM + rp) * DDIM;
        pb = pd = teacher + ((size_t)(b * VDIM + v) * PDIM + p) * DDIM;
    } else {
        target = 2;
        int t = w - 3584;
        int i = t >> 11, rem = t & 2047;
        int b = rem >> 10, r = (rem >> 2) & 255, k = rem & 3;
        int sp = shared_perm[r];
        int e = g_topk[((b << 8) + r) * 4 + k];
        int v = 2 * (e >> 12) + 1, p = e & (PDIM - 1);
        pa = teacher + ((size_t)(b * VDIM + c_ST[i]) * PDIM + sp) * DDIM;
        pc = student + ((size_t)(b * 4 + c_SS[i]) * PDIM + sp) * DDIM;
        pb = pd = teacher + ((size_t)(b * VDIM + v) * PDIM + p) * DDIM;
    }

    float dt[16], ds[16];
    bool same = (pb == pd);
    #pragma unroll
    for (int j = 0; j < 4; j++) {
        int idx = sub * 4 + j * 256;
        float4 A  = *(const float4*)(pa + idx);
        float4 Bv = *(const float4*)(pb + idx);
        float4 C  = *(const float4*)(pc + idx);
        float4 Dv = same ? Bv : *(const float4*)(pd + idx);
        dt[4 * j + 0] = A.x - Bv.x; dt[4 * j + 1] = A.y - Bv.y;
        dt[4 * j + 2] = A.z - Bv.z; dt[4 * j + 3] = A.w - Bv.w;
        ds[4 * j + 0] = C.x - Dv.x; ds[4 * j + 1] = C.y - Dv.y;
        ds[4 * j + 2] = C.z - Dv.z; ds[4 * j + 3] = C.w - Dv.w;
    }

    float mt = -3.4e38f, ms = -3.4e38f;
    #pragma unroll
    for (int i = 0; i < 16; i++) { mt = fmaxf(mt, dt[i]); ms = fmaxf(ms, ds[i]); }
    #pragma unroll
    for (int o = 16; o; o >>= 1) {
        mt = fmaxf(mt, __shfl_xor_sync(0xffffffffu, mt, o));
        ms = fmaxf(ms, __shfl_xor_sync(0xffffffffu, ms, o));
    }
    if (lane == 0) { r0[grp][w2] = mt; r1[grp][w2] = ms; }
    __syncthreads();
    mt = fmaxf(r0[grp][0], r0[grp][1]);
    ms = fmaxf(r1[grp][0], r1[grp][1]);

    float st = 0.f, ssum = 0.f;
    #pragma unroll
    for (int i = 0; i < 16; i++) { st += __expf(dt[i] - mt); ssum += __expf(ds[i] - ms); }
    #pragma unroll
    for (int o = 16; o; o >>= 1) {
        st   += __shfl_xor_sync(0xffffffffu, st, o);
        ssum += __shfl_xor_sync(0xffffffffu, ssum, o);
    }
    __syncthreads();
    if (lane == 0) { r0[grp][w2] = st; r1[grp][w2] = ssum; }
    __syncthreads();
    float lset = mt + __logf(r0[grp][0] + r0[grp][1]);
    float lses = ms + __logf(r1[grp][0] + r1[grp][1]);

    float acc = 0.f;
    #pragma unroll
    for (int i = 0; i < 16; i++) acc += __expf(dt[i] - lset) * (dt[i] - ds[i]);
    #pragma unroll
    for (int o = 16; o; o >>= 1) acc += __shfl_xor_sync(0xffffffffu, acc, o);
    __syncthreads();
    if (lane == 0) r0[grp][w2] = acc;
    __syncthreads();

    if (sub == 0) {
        float kl = (r0[grp][0] + r0[grp][1]) - lset + lses;
        float ax = fabsf(kl);
        float sl = (ax < 0.5f) ? kl * kl : (ax - 0.25f);   // smooth_l1, beta=0.5
        atomicAdd(&sacc[target], sl);
    }
    __syncthreads();
    if (tid < 3) atomicAdd(&g_accum[tid], sacc[tid]);

    // last-arriving block folds the final combine
    __syncthreads();
    if (tid == 0) {
        __threadfence();
        unsigned t = atomicAdd(&g_done, 1);
        if (t == gridDim.x - 1) {
            __threadfence();
            out[0] = g_accum[0] * (1.0f / 1536.0f)
                   + g_accum[1] * (1.0f / 2048.0f)
                   + g_accum[2] * (1.0f / 6144.0f);
            g_done = 0;
        }
    }
}

// ---------------------------------------------------------------------------
extern "C" void kernel_launch(void* const* d_in, const int* in_sizes, int n_in,
                              void* d_out, int out_size) {
    const float* teacher     = (const float*)d_in[0];
    const float* student     = (const float*)d_in[1];
    const int*   ref_perm    = (const int*)d_in[2];
    const int*   shared_perm = (const int*)d_in[3];
    float* out = (float*)d_out;

    cudaFuncSetAttribute(k_gemm, cudaFuncAttributeMaxDynamicSharedMemorySize, GEMM_SMEM);

    k_convert<<<BDIM * NREF, 128>>>(teacher, ref_perm);
    k_gemm<<<dim3(EN / 128, 1, BDIM), 512, GEMM_SMEM>>>(teacher);
    k_select<<<dim3(NREF, BDIM), 256>>>(teacher, ref_perm);
    k_loss<<<9728 / 4, 256>>>(teacher, student, ref_perm, shared_perm, out);
}

// round 14
// speedup vs baseline: 1.1104x; 1.0407x over previous
#include <cuda_runtime.h>
#include <cuda_bf16.h>
#include <cstdint>

// Problem constants
#define BDIM 2
#define VDIM 8
#define PDIM 4096
#define DDIM 1024
#define NREF 256
#define EN   16384
#define NCAND 8

// Scratch (device globals: allocation-free)
__device__ __nv_bfloat16 g_abf[BDIM * NREF * DDIM];   // 1 MB bf16 gathered refs
__device__ __nv_bfloat16 g_sim[BDIM * NREF * EN];     // 16.8 MB bf16 sims
__device__ int   g_topk[BDIM * NREF * 4];
__device__ float g_accum[3];
__device__ unsigned g_done;

__constant__ int c_ST[3] = {2, 4, 6};   // SHARED_TEACHER
__constant__ int c_SS[3] = {1, 2, 3};   // SHARED_STUDENT

__device__ __forceinline__ void ins4(float x, int e, float* v, int* id) {
    if (x <= v[3]) return;
    v[3] = x; id[3] = e;
    #pragma unroll
    for (int j = 3; j >= 1; j--) {
        if (v[j] > v[j - 1]) {
            float tv = v[j]; v[j] = v[j - 1]; v[j - 1] = tv;
            int ti = id[j]; id[j] = id[j - 1]; id[j - 1] = ti;
        }
    }
}

__device__ __forceinline__ void ins8(float x, int e, float* v, int* id) {
    if (x <= v[7]) return;
    v[7] = x; id[7] = e;
    #pragma unroll
    for (int j = 7; j >= 1; j--) {
        if (v[j] > v[j - 1]) {
            float tv = v[j]; v[j] = v[j - 1]; v[j - 1] = tv;
            int ti = id[j]; id[j] = id[j - 1]; id[j - 1] = ti;
        }
    }
}

// ---------------------------------------------------------------------------
// K0: convert gathered REF rows only to bf16 (A side; 1 MB, trivial)
// ---------------------------------------------------------------------------
__global__ void __launch_bounds__(128)
k_convert(const float* __restrict__ teacher, const int* __restrict__ ref_perm) {
    const int id  = blockIdx.x;              // [0, BDIM*NREF)
    const int tid = threadIdx.x;
    int b = id >> 8, r = id & 255;
    const float* src = teacher + ((size_t)(b * VDIM) * PDIM + ref_perm[r]) * DDIM;
    __nv_bfloat16* dst = g_abf + (size_t)id * DDIM;

    float4 x0 = ((const float4*)src)[tid * 2];
    float4 x1 = ((const float4*)src)[tid * 2 + 1];
    __nv_bfloat162 h0, h1, h2, h3;
    h0.x = __float2bfloat16(x0.x); h0.y = __float2bfloat16(x0.y);
    h1.x = __float2bfloat16(x0.z); h1.y = __float2bfloat16(x0.w);
    h2.x = __float2bfloat16(x1.x); h2.y = __float2bfloat16(x1.y);
    h3.x = __float2bfloat16(x1.z); h3.y = __float2bfloat16(x1.w);
    uint4 pk;
    pk.x = *(uint32_t*)&h0; pk.y = *(uint32_t*)&h1;
    pk.z = *(uint32_t*)&h2; pk.w = *(uint32_t*)&h3;
    ((uint4*)dst)[tid] = pk;
}

// ---------------------------------------------------------------------------
// K1: bf16 GEMM, 256x64 CTA tile (M covers all refs; B read once from f32
//     teacher via cp.async + in-smem f32->bf16 convert + inline exact norms).
//     256 threads, 8 warps (4 M x 2 N), warp tile 64x32, 3-stage pipeline,
//     OCCUPANCY 2 (co-resident CTA hides barrier/convert stalls).
// ---------------------------------------------------------------------------
#define NKT   (DDIM / 32)        // 32 k-tiles
#define STAGES 3
#define AROWB 80                 // A bf16: 64 data + 16 pad
#define BF32ROWB 144             // B f32: 128 data + 16 pad
#define A_STAGE 20480            // 256 * 80
#define BF32_STAGE 9216          // 64 * 144
#define BBF_STAGE 5120           // 64 * 80
#define ABASE 0
#define BF32BASE (STAGES * A_STAGE)                  // 61440
#define BBFBASE (BF32BASE + STAGES * BF32_STAGE)     // 89088
#define GEMM_SMEM (BBFBASE + 2 * BBF_STAGE)          // 99328

__device__ __forceinline__ void cp_async16(uint32_t dst, const void* src) {
    asm volatile("cp.async.cg.shared.global [%0], [%1], 16;" :: "r"(dst), "l"(src));
}

__global__ void __launch_bounds__(256, 2)
k_gemm(const float* __restrict__ teacher) {
    extern __shared__ __align__(16) uint8_t smem[];
    __shared__ float s_inv[64];

    const int b     = blockIdx.z;
    const int ebase = blockIdx.x * 64;
    const int tid   = threadIdx.x;
    const int lane  = tid & 31;
    const int wid   = tid >> 5;          // 0..7
    const int wm    = (wid >> 1) * 64;   // 4 M-groups of 64
    const int wn    = (wid & 1) * 32;    // 2 N-groups of 32
    const uint32_t sbase = (uint32_t)__cvta_generic_to_shared(smem);

    const int v     = 2 * (ebase >> 12) + 1;      // EXTRA_FRAMES {1,3,5,7}
    const int pbase = ebase & (PDIM - 1);

    // A loaders: 4 chunks/thread (256 rows x 4 chunks of 16B = 1024)
    const char* gA[4]; uint32_t sA[4];
    #pragma unroll
    for (int s = 0; s < 4; s++) {
        int c = tid + s * 256;
        int row = c >> 2, off = (c & 3) * 16;
        gA[s] = (const char*)(g_abf + ((size_t)(b * NREF + row)) * DDIM) + off;
        sA[s] = (uint32_t)(ABASE + row * AROWB + off);
    }
    // B f32 loaders: 2 chunks/thread (64 rows x 8 chunks of 16B = 512)
    const char* gB[2]; uint32_t sB[2];
    #pragma unroll
    for (int s = 0; s < 2; s++) {
        int c = tid + s * 256;
        int row = c >> 3, off = (c & 7) * 16;
        gB[s] = (const char*)(teacher + ((size_t)(b * VDIM + v) * PDIM + pbase + row) * DDIM) + off;
        sB[s] = (uint32_t)(BF32BASE + row * BF32ROWB + off);
    }

    float acc[4][4][4];
    #pragma unroll
    for (int i = 0; i < 4; i++)
        #pragma unroll
        for (int j = 0; j < 4; j++)
            #pragma unroll
            for (int k = 0; k < 4; k++) acc[i][j][k] = 0.f;

    // ldmatrix lane addressing (byte offsets)
    const int xr = (lane & 7) + ((lane >> 3) & 1) * 8;
    const int xk = (lane >> 4) * 16;
    uint32_t a_off[4], b_off[2];
    #pragma unroll
    for (int mi = 0; mi < 4; mi++)
        a_off[mi] = (uint32_t)(ABASE + (wm + mi * 16 + xr) * AROWB + xk);
    #pragma unroll
    for (int nj = 0; nj < 2; nj++)
        b_off[nj] = (uint32_t)(BBFBASE + (wn + nj * 16 + xr) * AROWB + xk);

    // convert-phase indices: 4 threads per B row (64 rows x 4 = 256)
    const int crow = tid >> 2;
    const int cseg = tid & 3;
    float ssq = 0.f;

    // prologue: stages 0..1
    #pragma unroll
    for (int s = 0; s < STAGES - 1; s++) {
        #pragma unroll
        for (int q = 0; q < 4; q++)
            cp_async16(sbase + s * A_STAGE + sA[q], gA[q] + s * 64);
        #pragma unroll
        for (int q = 0; q < 2; q++)
            cp_async16(sbase + s * BF32_STAGE + sB[q], gB[q] + s * 128);
        asm volatile("cp.async.commit_group;");
    }

    for (int kt = 0; kt < NKT; kt++) {
        asm volatile("cp.async.wait_group %0;" :: "n"(STAGES - 2));
        __syncthreads();

        int wst = kt + STAGES - 1;
        if (wst < NKT) {
            int st = wst % STAGES;
            #pragma unroll
            for (int q = 0; q < 4; q++)
                cp_async16(sbase + st * A_STAGE + sA[q], gA[q] + wst * 64);
            #pragma unroll
            for (int q = 0; q < 2; q++)
                cp_async16(sbase + st * BF32_STAGE + sB[q], gB[q] + wst * 128);
        }
        asm volatile("cp.async.commit_group;");

        const int stg = kt % STAGES;
        // convert: read 8 f32 from B f32 stage, write 8 bf16, accumulate ssq
        {
            const float* fsrc = (const float*)(smem + BF32BASE + stg * BF32_STAGE
                                               + crow * BF32ROWB + cseg * 32);
            float4 x0 = ((const float4*)fsrc)[0];
            float4 x1 = ((const float4*)fsrc)[1];
            ssq += x0.x * x0.x + x0.y * x0.y + x0.z * x0.z + x0.w * x0.w
                 + x1.x * x1.x + x1.y * x1.y + x1.z * x1.z + x1.w * x1.w;
            __nv_bfloat162 h0, h1, h2, h3;
            h0.x = __float2bfloat16(x0.x); h0.y = __float2bfloat16(x0.y);
            h1.x = __float2bfloat16(x0.z); h1.y = __float2bfloat16(x0.w);
            h2.x = __float2bfloat16(x1.x); h2.y = __float2bfloat16(x1.y);
            h3.x = __float2bfloat16(x1.z); h3.y = __float2bfloat16(x1.w);
            uint4 pk;
            pk.x = *(uint32_t*)&h0; pk.y = *(uint32_t*)&h1;
            pk.z = *(uint32_t*)&h2; pk.w = *(uint32_t*)&h3;
            *(uint4*)(smem + BBFBASE + (kt & 1) * BBF_STAGE + crow * AROWB + cseg * 16) = pk;
        }
        __syncthreads();

        const uint32_t astg = (uint32_t)(stg * A_STAGE);
        const uint32_t bbuf = (uint32_t)((kt & 1) * BBF_STAGE);
        #pragma unroll
        for (int ks = 0; ks < 64; ks += 32) {
            uint32_t af[4][4], bf[2][4];
            #pragma unroll
            for (int mi = 0; mi < 4; mi++) {
                asm volatile("ldmatrix.sync.aligned.m8n8.x4.shared.b16 {%0,%1,%2,%3}, [%4];"
                    : "=r"(af[mi][0]), "=r"(af[mi][1]), "=r"(af[mi][2]), "=r"(af[mi][3])
                    : "r"(sbase + astg + a_off[mi] + ks));
            }
            #pragma unroll
            for (int nj = 0; nj < 2; nj++) {
                asm volatile("ldmatrix.sync.aligned.m8n8.x4.shared.b16 {%0,%1,%2,%3}, [%4];"
                    : "=r"(bf[nj][0]), "=r"(bf[nj][1]), "=r"(bf[nj][2]), "=r"(bf[nj][3])
                    : "r"(sbase + bbuf + b_off[nj] + ks));
            }
            #pragma unroll
            for (int mi = 0; mi < 4; mi++) {
                #pragma unroll
                for (int nj = 0; nj < 4; nj++) {
                    uint32_t bb0 = bf[nj >> 1][nj & 1];
                    uint32_t bb1 = bf[nj >> 1][(nj & 1) + 2];
                    asm volatile(
                        "mma.sync.aligned.m16n8k16.row.col.f32.bf16.bf16.f32 "
                        "{%0,%1,%2,%3}, {%4,%5,%6,%7}, {%8,%9}, {%0,%1,%2,%3};"
                        : "+f"(acc[mi][nj][0]), "+f"(acc[mi][nj][1]),
                          "+f"(acc[mi][nj][2]), "+f"(acc[mi][nj][3])
                        : "r"(af[mi][0]), "r"(af[mi][1]), "r"(af[mi][2]), "r"(af[mi][3]),
                          "r"(bb0), "r"(bb1));
                }
            }
        }
    }

    // exact B-row inverse norms: 4 threads per row
    ssq += __shfl_xor_sync(0xffffffffu, ssq, 1);
    ssq += __shfl_xor_sync(0xffffffffu, ssq, 2);
    if ((tid & 3) == 0) s_inv[crow] = 1.0f / fmaxf(sqrtf(ssq), 1e-12f);
    __syncthreads();

    // epilogue: scale by inv_norm[e], write bf16 sims (4B packed stores)
    #pragma unroll
    for (int mi = 0; mi < 4; mi++) {
        int r = wm + mi * 16 + (lane >> 2);
        __nv_bfloat16* orow = g_sim + ((size_t)(b * NREF + r)) * EN + ebase;
        #pragma unroll
        for (int nj = 0; nj < 4; nj++) {
            int c = wn + nj * 8 + (lane & 3) * 2;
            __nv_bfloat162 h0, h1;
            h0.x = __float2bfloat16(acc[mi][nj][0] * s_inv[c]);
            h0.y = __float2bfloat16(acc[mi][nj][1] * s_inv[c + 1]);
            h1.x = __float2bfloat16(acc[mi][nj][2] * s_inv[c]);
            h1.y = __float2bfloat16(acc[mi][nj][3] * s_inv[c + 1]);
            *(uint32_t*)(orow + c)          = *(uint32_t*)&h0;
            *(uint32_t*)(orow + 8 * EN + c) = *(uint32_t*)&h1;
        }
    }
}

// ---------------------------------------------------------------------------
// K2: per (b,r): top-8 candidates from bf16 sims (vectorized 16B loads),
//     then exact fp32 re-rank -> exact top-4 indices.
// ---------------------------------------------------------------------------
__global__ void __launch_bounds__(256)
k_select(const float* __restrict__ teacher, const int* __restrict__ ref_perm) {
    int r = blockIdx.x, b = blockIdx.y, tid = threadIdx.x;
    int w = tid >> 5, lane = tid & 31;
    const __nv_bfloat16* row = g_sim + ((size_t)(b * NREF + r)) * EN;

    if (r == 0 && b == 0 && tid < 3) g_accum[tid] = 0.f;

    float v[4] = {-3.4e38f, -3.4e38f, -3.4e38f, -3.4e38f};
    int id[4] = {0, 0, 0, 0};
    #pragma unroll
    for (int k = 0; k < 8; k++) {
        int base = (k * 256 + tid) * 8;
        uint4 pk = *(const uint4*)(row + base);
        uint32_t uu[4] = {pk.x, pk.y, pk.z, pk.w};
        #pragma unroll
        for (int q = 0; q < 4; q++) {
            __nv_bfloat162 h = *(__nv_bfloat162*)&uu[q];
            ins4(__bfloat162float(h.x), base + q * 2,     v, id);
            ins4(__bfloat162float(h.y), base + q * 2 + 1, v, id);
        }
    }

    __shared__ float sv[1024];
    __shared__ int   si[1024];
    __shared__ int   s_cand[NCAND];
    __shared__ float s_sim[NCAND];
    __shared__ int   s_e[NCAND];

    #pragma unroll
    for (int j = 0; j < 4; j++) { sv[tid * 4 + j] = v[j]; si[tid * 4 + j] = id[j]; }
    __syncthreads();

    if (tid < 32) {
        float v2[4] = {-3.4e38f, -3.4e38f, -3.4e38f, -3.4e38f};
        int id2[4] = {0, 0, 0, 0};
        for (int t = tid * 32; t < tid * 32 + 32; t++) ins4(sv[t], si[t], v2, id2);
        __syncwarp();
        #pragma unroll
        for (int j = 0; j < 4; j++) { sv[tid * 4 + j] = v2[j]; si[tid * 4 + j] = id2[j]; }
        __syncwarp();
        if (tid == 0) {
            float v3[8]; int id3[8];
            #pragma unroll
            for (int j = 0; j < 8; j++) { v3[j] = -3.4e38f; id3[j] = 0; }
            for (int t = 0; t < 128; t++) ins8(sv[t], si[t], v3, id3);
            #pragma unroll
            for (int j = 0; j < 8; j++) s_cand[j] = id3[j];
        }
    }
    __syncthreads();

    int e = s_cand[w];
    int vv = 2 * (e >> 12) + 1, p = e & (PDIM - 1);
    const float* er = teacher + ((size_t)(b * VDIM + vv) * PDIM + p) * DDIM;
    const float* rr = teacher + ((size_t)(b * VDIM) * PDIM + ref_perm[r]) * DDIM;

    float dot = 0.f, ss = 0.f;
    #pragma unroll
    for (int j = 0; j < 8; j++) {
        int idx = lane * 4 + j * 128;
        float4 x = *(const float4*)(er + idx);
        float4 y = *(const float4*)(rr + idx);
        dot += x.x * y.x + x.y * y.y + x.z * y.z + x.w * y.w;
        ss  += x.x * x.x + x.y * x.y + x.z * x.z + x.w * x.w;
    }
    #pragma unroll
    for (int o = 16; o; o >>= 1) {
        dot += __shfl_xor_sync(0xffffffffu, dot, o);
        ss  += __shfl_xor_sync(0xffffffffu, ss, o);
    }
    if (lane == 0) {
        s_sim[w] = dot / fmaxf(sqrtf(ss), 1e-12f);
        s_e[w] = e;
    }
    __syncthreads();

    if (tid == 0) {
        bool used[NCAND] = {false, false, false, false, false, false, false, false};
        #pragma unroll
        for (int j = 0; j < 4; j++) {
            int best = -1;
            float bvv = -3.4e38f; int be = 0x7fffffff;
            for (int t = 0; t < NCAND; t++) {
                if (used[t]) continue;
                if (s_sim[t] > bvv || (s_sim[t] == bvv && s_e[t] < be)) {
                    bvv = s_sim[t]; be = s_e[t]; best = t;
                }
            }
            used[best] = true;
            g_topk[(b * NREF + r) * 4 + j] = s_e[best];
        }
    }
}

// ---------------------------------------------------------------------------
// K3: KL + smooth-L1 losses, 64 threads per row-pair, fast-math exp/log;
//     last-arriving block writes the final scalar.
// ---------------------------------------------------------------------------
__global__ void __launch_bounds__(256)
k_loss(const float* __restrict__ teacher, const float* __restrict__ student,
       const int* __restrict__ ref_perm, const int* __restrict__ shared_perm,
       float* __restrict__ out) {
    __shared__ float sacc[3];
    __shared__ float r0[4][2], r1[4][2];
    int tid = threadIdx.x;
    if (tid < 3) sacc[tid] = 0.f;

    int grp  = tid >> 6;
    int sub  = tid & 63;
    int w2   = (tid >> 5) & 1;
    int lane = tid & 31;
    int w    = blockIdx.x * 4 + grp;

    const float *pa, *pb, *pc, *pd;
    int target;
    if (w < 1536) {
        target = 0;
        int i = w / 512, rem = w & 511;
        int b = rem >> 8, r = rem & 255;
        int rp = ref_perm[r], sp = shared_perm[r];
        pa = teacher + ((size_t)(b * VDIM) * PDIM + rp) * DDIM;
        pb = teacher + ((size_t)(b * VDIM + c_ST[i]) * PDIM + sp) * DDIM;
        pc = student + ((size_t)(b * 4) * PDIM + rp) * DDIM;
        pd = student + ((size_t)(b * 4 + c_SS[i]) * PDIM + sp) * DDIM;
    } else if (w < 3584) {
        target = 1;
        int t = w - 1536;
        int b = t >> 10, rem = t & 1023;
        int r = rem >> 2, k = rem & 3;
        int rp = ref_perm[r];
        int e = g_topk[((b << 8) + r) * 4 + k];
        int v = 2 * (e >> 12) + 1, p = e & (PDIM - 1);
        pa = teacher + ((size_t)(b * VDIM) * PDIM + rp) * DDIM;
        pc = student + ((size_t)(b * 4) * PDIM + rp) * DDIM;
        pb = pd = teacher + ((size_t)(b * VDIM + v) * PDIM + p) * DDIM;
    } else {
        target = 2;
        int t = w - 3584;
        int i = t >> 11, rem = t & 2047;
        int b = rem >> 10, r = (rem >> 2) & 255, k = rem & 3;
        int sp = shared_perm[r];
        int e = g_topk[((b << 8) + r) * 4 + k];
        int v = 2 * (e >> 12) + 1, p = e & (PDIM - 1);
        pa = teacher + ((size_t)(b * VDIM + c_ST[i]) * PDIM + sp) * DDIM;
        pc = student + ((size_t)(b * 4 + c_SS[i]) * PDIM + sp) * DDIM;
        pb = pd = teacher + ((size_t)(b * VDIM + v) * PDIM + p) * DDIM;
    }

    float dt[16], ds[16];
    bool same = (pb == pd);
    #pragma unroll
    for (int j = 0; j < 4; j++) {
        int idx = sub * 4 + j * 256;
        float4 A  = *(const float4*)(pa + idx);
        float4 Bv = *(const float4*)(pb + idx);
        float4 C  = *(const float4*)(pc + idx);
        float4 Dv = same ? Bv : *(const float4*)(pd + idx);
        dt[4 * j + 0] = A.x - Bv.x; dt[4 * j + 1] = A.y - Bv.y;
        dt[4 * j + 2] = A.z - Bv.z; dt[4 * j + 3] = A.w - Bv.w;
        ds[4 * j + 0] = C.x - Dv.x; ds[4 * j + 1] = C.y - Dv.y;
        ds[4 * j + 2] = C.z - Dv.z; ds[4 * j + 3] = C.w - Dv.w;
    }

    float mt = -3.4e38f, ms = -3.4e38f;
    #pragma unroll
    for (int i = 0; i < 16; i++) { mt = fmaxf(mt, dt[i]); ms = fmaxf(ms, ds[i]); }
    #pragma unroll
    for (int o = 16; o; o >>= 1) {
        mt = fmaxf(mt, __shfl_xor_sync(0xffffffffu, mt, o));
        ms = fmaxf(ms, __shfl_xor_sync(0xffffffffu, ms, o));
    }
    if (lane == 0) { r0[grp][w2] = mt; r1[grp][w2] = ms; }
    __syncthreads();
    mt = fmaxf(r0[grp][0], r0[grp][1]);
    ms = fmaxf(r1[grp][0], r1[grp][1]);

    float st = 0.f, ssum = 0.f;
    #pragma unroll
    for (int i = 0; i < 16; i++) { st += __expf(dt[i] - mt); ssum += __expf(ds[i] - ms); }
    #pragma unroll
    for (int o = 16; o; o >>= 1) {
        st   += __shfl_xor_sync(0xffffffffu, st, o);
        ssum += __shfl_xor_sync(0xffffffffu, ssum, o);
    }
    __syncthreads();
    if (lane == 0) { r0[grp][w2] = st; r1[grp][w2] = ssum; }
    __syncthreads();
    float lset = mt + __logf(r0[grp][0] + r0[grp][1]);
    float lses = ms + __logf(r1[grp][0] + r1[grp][1]);

    float acc = 0.f;
    #pragma unroll
    for (int i = 0; i < 16; i++) acc += __expf(dt[i] - lset) * (dt[i] - ds[i]);
    #pragma unroll
    for (int o = 16; o; o >>= 1) acc += __shfl_xor_sync(0xffffffffu, acc, o);
    __syncthreads();
    if (lane == 0) r0[grp][w2] = acc;
    __syncthreads();

    if (sub == 0) {
        float kl = (r0[grp][0] + r0[grp][1]) - lset + lses;
        float ax = fabsf(kl);
        float sl = (ax < 0.5f) ? kl * kl : (ax - 0.25f);   // smooth_l1, beta=0.5
        atomicAdd(&sacc[target], sl);
    }
    __syncthreads();
    if (tid < 3) atomicAdd(&g_accum[tid], sacc[tid]);

    // last-arriving block folds the final combine
    __syncthreads();
    if (tid == 0) {
        __threadfence();
        unsigned t = atomicAdd(&g_done, 1);
        if (t == gridDim.x - 1) {
            __threadfence();
            out[0] = g_accum[0] * (1.0f / 1536.0f)
                   + g_accum[1] * (1.0f / 2048.0f)
                   + g_accum[2] * (1.0f / 6144.0f);
            g_done = 0;
        }
    }
}

// ---------------------------------------------------------------------------
extern "C" void kernel_launch(void* const* d_in, const int* in_sizes, int n_in,
                              void* d_out, int out_size) {
    const float* teacher     = (const float*)d_in[0];
    const float* student     = (const float*)d_in[1];
    const int*   ref_perm    = (const int*)d_in[2];
    const int*   shared_perm = (const int*)d_in[3];
    float* out = (float*)d_out;

    cudaFuncSetAttribute(k_gemm, cudaFuncAttributeMaxDynamicSharedMemorySize, GEMM_SMEM);

    k_convert<<<BDIM * NREF, 128>>>(teacher, ref_perm);
    k_gemm<<<dim3(EN / 64, 1, BDIM), 256, GEMM_SMEM>>>(teacher);
    k_select<<<dim3(NREF, BDIM), 256>>>(teacher, ref_perm);
    k_loss<<<9728 / 4, 256>>>(teacher, student, ref_perm, shared_perm, out);
}

// round 15
// speedup vs baseline: 1.1471x; 1.0331x over previous
#include <cuda_runtime.h>
#include <cuda_bf16.h>
#include <cstdint>

// Problem constants
#define BDIM 2
#define VDIM 8
#define PDIM 4096
#define DDIM 1024
#define NREF 256
#define EN   16384
#define NCAND 8

// Scratch (device globals: allocation-free)
__device__ __nv_bfloat16 g_abf[BDIM * NREF * DDIM];   // 1 MB bf16 gathered refs
__device__ __nv_bfloat16 g_sim[BDIM * NREF * EN];     // 16.8 MB bf16 sims
__device__ int   g_topk[BDIM * NREF * 4];
__device__ float g_accum[3];
__device__ unsigned g_done;

__constant__ int c_ST[3] = {2, 4, 6};   // SHARED_TEACHER
__constant__ int c_SS[3] = {1, 2, 3};   // SHARED_STUDENT

__device__ __forceinline__ void ins4(float x, int e, float* v, int* id) {
    if (x <= v[3]) return;
    v[3] = x; id[3] = e;
    #pragma unroll
    for (int j = 3; j >= 1; j--) {
        if (v[j] > v[j - 1]) {
            float tv = v[j]; v[j] = v[j - 1]; v[j - 1] = tv;
            int ti = id[j]; id[j] = id[j - 1]; id[j - 1] = ti;
        }
    }
}

__device__ __forceinline__ void ins8(float x, int e, float* v, int* id) {
    if (x <= v[7]) return;
    v[7] = x; id[7] = e;
    #pragma unroll
    for (int j = 7; j >= 1; j--) {
        if (v[j] > v[j - 1]) {
            float tv = v[j]; v[j] = v[j - 1]; v[j - 1] = tv;
            int ti = id[j]; id[j] = id[j - 1]; id[j - 1] = ti;
        }
    }
}

// ---------------------------------------------------------------------------
// K0: convert gathered REF rows only to bf16 (A side; 1 MB, trivial)
// ---------------------------------------------------------------------------
__global__ void __launch_bounds__(128)
k_convert(const float* __restrict__ teacher, const int* __restrict__ ref_perm) {
    const int id  = blockIdx.x;              // [0, BDIM*NREF)
    const int tid = threadIdx.x;
    int b = id >> 8, r = id & 255;
    const float* src = teacher + ((size_t)(b * VDIM) * PDIM + ref_perm[r]) * DDIM;
    __nv_bfloat16* dst = g_abf + (size_t)id * DDIM;

    float4 x0 = ((const float4*)src)[tid * 2];
    float4 x1 = ((const float4*)src)[tid * 2 + 1];
    __nv_bfloat162 h0, h1, h2, h3;
    h0.x = __float2bfloat16(x0.x); h0.y = __float2bfloat16(x0.y);
    h1.x = __float2bfloat16(x0.z); h1.y = __float2bfloat16(x0.w);
    h2.x = __float2bfloat16(x1.x); h2.y = __float2bfloat16(x1.y);
    h3.x = __float2bfloat16(x1.z); h3.y = __float2bfloat16(x1.w);
    uint4 pk;
    pk.x = *(uint32_t*)&h0; pk.y = *(uint32_t*)&h1;
    pk.z = *(uint32_t*)&h2; pk.w = *(uint32_t*)&h3;
    ((uint4*)dst)[tid] = pk;
}

// ---------------------------------------------------------------------------
// K1: bf16 GEMM, 256x64 CTA tile, B direct from f32 teacher (cp.async) with
//     SOFTWARE-PIPELINED in-smem convert: MMA(kt) runs between the same
//     barriers as convert(kt+1) -> ONE __syncthreads per k-tile.
//     256 threads, 8 warps (4 M x 2 N), warp tile 64x32, occ 2.
// ---------------------------------------------------------------------------
#define NKT   (DDIM / 32)        // 32 k-tiles
#define STAGES 3
#define AROWB 80                 // A bf16: 64 data + 16 pad
#define BF32ROWB 144             // B f32: 128 data + 16 pad
#define A_STAGE 20480            // 256 * 80
#define BF32_STAGE 9216          // 64 * 144
#define BBF_STAGE 5120           // 64 * 80
#define ABASE 0
#define BF32BASE (STAGES * A_STAGE)                  // 61440
#define BBFBASE (BF32BASE + STAGES * BF32_STAGE)     // 89088
#define GEMM_SMEM (BBFBASE + 2 * BBF_STAGE)          // 99328

__device__ __forceinline__ void cp_async16(uint32_t dst, const void* src) {
    asm volatile("cp.async.cg.shared.global [%0], [%1], 16;" :: "r"(dst), "l"(src));
}

__global__ void __launch_bounds__(256, 2)
k_gemm(const float* __restrict__ teacher) {
    extern __shared__ __align__(16) uint8_t smem[];
    __shared__ float s_inv[64];

    const int b     = blockIdx.z;
    const int ebase = blockIdx.x * 64;
    const int tid   = threadIdx.x;
    const int lane  = tid & 31;
    const int wid   = tid >> 5;          // 0..7
    const int wm    = (wid >> 1) * 64;
    const int wn    = (wid & 1) * 32;
    const uint32_t sbase = (uint32_t)__cvta_generic_to_shared(smem);

    const int v     = 2 * (ebase >> 12) + 1;      // EXTRA_FRAMES {1,3,5,7}
    const int pbase = ebase & (PDIM - 1);

    // A loaders: 4 chunks/thread
    const char* gA[4]; uint32_t sA[4];
    #pragma unroll
    for (int s = 0; s < 4; s++) {
        int c = tid + s * 256;
        int row = c >> 2, off = (c & 3) * 16;
        gA[s] = (const char*)(g_abf + ((size_t)(b * NREF + row)) * DDIM) + off;
        sA[s] = (uint32_t)(ABASE + row * AROWB + off);
    }
    // B f32 loaders: 2 chunks/thread
    const char* gB[2]; uint32_t sB[2];
    #pragma unroll
    for (int s = 0; s < 2; s++) {
        int c = tid + s * 256;
        int row = c >> 3, off = (c & 7) * 16;
        gB[s] = (const char*)(teacher + ((size_t)(b * VDIM + v) * PDIM + pbase + row) * DDIM) + off;
        sB[s] = (uint32_t)(BF32BASE + row * BF32ROWB + off);
    }

    float acc[4][4][4];
    #pragma unroll
    for (int i = 0; i < 4; i++)
        #pragma unroll
        for (int j = 0; j < 4; j++)
            #pragma unroll
            for (int k = 0; k < 4; k++) acc[i][j][k] = 0.f;

    // ldmatrix lane addressing (byte offsets)
    const int xr = (lane & 7) + ((lane >> 3) & 1) * 8;
    const int xk = (lane >> 4) * 16;
    uint32_t a_off[4], b_off[2];
    #pragma unroll
    for (int mi = 0; mi < 4; mi++)
        a_off[mi] = (uint32_t)(ABASE + (wm + mi * 16 + xr) * AROWB + xk);
    #pragma unroll
    for (int nj = 0; nj < 2; nj++)
        b_off[nj] = (uint32_t)(BBFBASE + (wn + nj * 16 + xr) * AROWB + xk);

    // convert-phase indices: 4 threads per B row
    const int crow = tid >> 2;
    const int cseg = tid & 3;
    float ssq = 0.f;

    // convert helper (stage s -> bbf buffer bb)
    auto do_convert = [&](int s, int bb) {
        const float* fsrc = (const float*)(smem + BF32BASE + s * BF32_STAGE
                                           + crow * BF32ROWB + cseg * 32);
        float4 x0 = ((const float4*)fsrc)[0];
        float4 x1 = ((const float4*)fsrc)[1];
        ssq += x0.x * x0.x + x0.y * x0.y + x0.z * x0.z + x0.w * x0.w
             + x1.x * x1.x + x1.y * x1.y + x1.z * x1.z + x1.w * x1.w;
        __nv_bfloat162 h0, h1, h2, h3;
        h0.x = __float2bfloat16(x0.x); h0.y = __float2bfloat16(x0.y);
        h1.x = __float2bfloat16(x0.z); h1.y = __float2bfloat16(x0.w);
        h2.x = __float2bfloat16(x1.x); h2.y = __float2bfloat16(x1.y);
        h3.x = __float2bfloat16(x1.z); h3.y = __float2bfloat16(x1.w);
        uint4 pk;
        pk.x = *(uint32_t*)&h0; pk.y = *(uint32_t*)&h1;
        pk.z = *(uint32_t*)&h2; pk.w = *(uint32_t*)&h3;
        *(uint4*)(smem + BBFBASE + bb * BBF_STAGE + crow * AROWB + cseg * 16) = pk;
    };

    // prologue: issue stages 0,1; wait stage 0; convert stage0 -> bbf0
    #pragma unroll
    for (int s = 0; s < 2; s++) {
        #pragma unroll
        for (int q = 0; q < 4; q++)
            cp_async16(sbase + s * A_STAGE + sA[q], gA[q] + s * 64);
        #pragma unroll
        for (int q = 0; q < 2; q++)
            cp_async16(sbase + s * BF32_STAGE + sB[q], gB[q] + s * 128);
        asm volatile("cp.async.commit_group;");
    }
    asm volatile("cp.async.wait_group 1;");
    __syncthreads();                         // stage0 visible to all
    do_convert(0, 0);
    __syncthreads();

    for (int kt = 0; kt < NKT; kt++) {
        // issue cp for stage kt+2
        int wst = kt + 2;
        if (wst < NKT) {
            int st = wst % STAGES;
            #pragma unroll
            for (int q = 0; q < 4; q++)
                cp_async16(sbase + st * A_STAGE + sA[q], gA[q] + wst * 64);
            #pragma unroll
            for (int q = 0; q < 2; q++)
                cp_async16(sbase + st * BF32_STAGE + sB[q], gB[q] + wst * 128);
        }
        asm volatile("cp.async.commit_group;");

        // MMA(kt): A stage kt%3 (arrived), bbf[kt&1] (converted+synced)
        const uint32_t astg = (uint32_t)((kt % STAGES) * A_STAGE);
        const uint32_t bbuf = (uint32_t)((kt & 1) * BBF_STAGE);
        #pragma unroll
        for (int ks = 0; ks < 64; ks += 32) {
            uint32_t af[4][4], bf[2][4];
            #pragma unroll
            for (int mi = 0; mi < 4; mi++) {
                asm volatile("ldmatrix.sync.aligned.m8n8.x4.shared.b16 {%0,%1,%2,%3}, [%4];"
                    : "=r"(af[mi][0]), "=r"(af[mi][1]), "=r"(af[mi][2]), "=r"(af[mi][3])
                    : "r"(sbase + astg + a_off[mi] + ks));
            }
            #pragma unroll
            for (int nj = 0; nj < 2; nj++) {
                asm volatile("ldmatrix.sync.aligned.m8n8.x4.shared.b16 {%0,%1,%2,%3}, [%4];"
                    : "=r"(bf[nj][0]), "=r"(bf[nj][1]), "=r"(bf[nj][2]), "=r"(bf[nj][3])
                    : "r"(sbase + bbuf + b_off[nj] + ks));
            }
            #pragma unroll
            for (int mi = 0; mi < 4; mi++) {
                #pragma unroll
                for (int nj = 0; nj < 4; nj++) {
                    uint32_t bb0 = bf[nj >> 1][nj & 1];
                    uint32_t bb1 = bf[nj >> 1][(nj & 1) + 2];
                    asm volatile(
                        "mma.sync.aligned.m16n8k16.row.col.f32.bf16.bf16.f32 "
                        "{%0,%1,%2,%3}, {%4,%5,%6,%7}, {%8,%9}, {%0,%1,%2,%3};"
                        : "+f"(acc[mi][nj][0]), "+f"(acc[mi][nj][1]),
                          "+f"(acc[mi][nj][2]), "+f"(acc[mi][nj][3])
                        : "r"(af[mi][0]), "r"(af[mi][1]), "r"(af[mi][2]), "r"(af[mi][3]),
                          "r"(bb0), "r"(bb1));
                }
            }
        }

        // convert(kt+1) into the OTHER bbf buffer (overlaps MMA across warps)
        if (kt + 1 < NKT) {
            asm volatile("cp.async.wait_group 1;");   // stage kt+1 arrived
            do_convert((kt + 1) % STAGES, (kt + 1) & 1);
        }
        __syncthreads();                              // one barrier per k-tile
    }

    // exact B-row inverse norms: 4 threads per row
    ssq += __shfl_xor_sync(0xffffffffu, ssq, 1);
    ssq += __shfl_xor_sync(0xffffffffu, ssq, 2);
    if ((tid & 3) == 0) s_inv[crow] = 1.0f / fmaxf(sqrtf(ssq), 1e-12f);
    __syncthreads();

    // epilogue: scale by inv_norm[e], write bf16 sims (4B packed stores)
    #pragma unroll
    for (int mi = 0; mi < 4; mi++) {
        int r = wm + mi * 16 + (lane >> 2);
        __nv_bfloat16* orow = g_sim + ((size_t)(b * NREF + r)) * EN + ebase;
        #pragma unroll
        for (int nj = 0; nj < 4; nj++) {
            int c = wn + nj * 8 + (lane & 3) * 2;
            __nv_bfloat162 h0, h1;
            h0.x = __float2bfloat16(acc[mi][nj][0] * s_inv[c]);
            h0.y = __float2bfloat16(acc[mi][nj][1] * s_inv[c + 1]);
            h1.x = __float2bfloat16(acc[mi][nj][2] * s_inv[c]);
            h1.y = __float2bfloat16(acc[mi][nj][3] * s_inv[c + 1]);
            *(uint32_t*)(orow + c)          = *(uint32_t*)&h0;
            *(uint32_t*)(orow + 8 * EN + c) = *(uint32_t*)&h1;
        }
    }
}

// ---------------------------------------------------------------------------
// K2: per (b,r): top-8 candidates from bf16 sims (vectorized 16B loads),
//     then exact fp32 re-rank -> exact top-4 indices.
// ---------------------------------------------------------------------------
__global__ void __launch_bounds__(256)
k_select(const float* __restrict__ teacher, const int* __restrict__ ref_perm) {
    int r = blockIdx.x, b = blockIdx.y, tid = threadIdx.x;
    int w = tid >> 5, lane = tid & 31;
    const __nv_bfloat16* row = g_sim + ((size_t)(b * NREF + r)) * EN;

    if (r == 0 && b == 0 && tid < 3) g_accum[tid] = 0.f;

    float v[4] = {-3.4e38f, -3.4e38f, -3.4e38f, -3.4e38f};
    int id[4] = {0, 0, 0, 0};
    #pragma unroll
    for (int k = 0; k < 8; k++) {
        int base = (k * 256 + tid) * 8;
        uint4 pk = *(const uint4*)(row + base);
        uint32_t uu[4] = {pk.x, pk.y, pk.z, pk.w};
        #pragma unroll
        for (int q = 0; q < 4; q++) {
            __nv_bfloat162 h = *(__nv_bfloat162*)&uu[q];
            ins4(__bfloat162float(h.x), base + q * 2,     v, id);
            ins4(__bfloat162float(h.y), base + q * 2 + 1, v, id);
        }
    }

    __shared__ float sv[1024];
    __shared__ int   si[1024];
    __shared__ int   s_cand[NCAND];
    __shared__ float s_sim[NCAND];
    __shared__ int   s_e[NCAND];

    #pragma unroll
    for (int j = 0; j < 4; j++) { sv[tid * 4 + j] = v[j]; si[tid * 4 + j] = id[j]; }
    __syncthreads();

    if (tid < 32) {
        float v2[4] = {-3.4e38f, -3.4e38f, -3.4e38f, -3.4e38f};
        int id2[4] = {0, 0, 0, 0};
        for (int t = tid * 32; t < tid * 32 + 32; t++) ins4(sv[t], si[t], v2, id2);
        __syncwarp();
        #pragma unroll
        for (int j = 0; j < 4; j++) { sv[tid * 4 + j] = v2[j]; si[tid * 4 + j] = id2[j]; }
        __syncwarp();
        if (tid == 0) {
            float v3[8]; int id3[8];
            #pragma unroll
            for (int j = 0; j < 8; j++) { v3[j] = -3.4e38f; id3[j] = 0; }
            for (int t = 0; t < 128; t++) ins8(sv[t], si[t], v3, id3);
            #pragma unroll
            for (int j = 0; j < 8; j++) s_cand[j] = id3[j];
        }
    }
    __syncthreads();

    int e = s_cand[w];
    int vv = 2 * (e >> 12) + 1, p = e & (PDIM - 1);
    const float* er = teacher + ((size_t)(b * VDIM + vv) * PDIM + p) * DDIM;
    const float* rr = teacher + ((size_t)(b * VDIM) * PDIM + ref_perm[r]) * DDIM;

    float dot = 0.f, ss = 0.f;
    #pragma unroll
    for (int j = 0; j < 8; j++) {
        int idx = lane * 4 + j * 128;
        float4 x = *(const float4*)(er + idx);
        float4 y = *(const float4*)(rr + idx);
        dot += x.x * y.x + x.y * y.y + x.z * y.z + x.w * y.w;
        ss  += x.x * x.x + x.y * x.y + x.z * x.z + x.w * x.w;
    }
    #pragma unroll
    for (int o = 16; o; o >>= 1) {
        dot += __shfl_xor_sync(0xffffffffu, dot, o);
        ss  += __shfl_xor_sync(0xffffffffu, ss, o);
    }
    if (lane == 0) {
        s_sim[w] = dot / fmaxf(sqrtf(ss), 1e-12f);
        s_e[w] = e;
    }
    __syncthreads();

    if (tid == 0) {
        bool used[NCAND] = {false, false, false, false, false, false, false, false};
        #pragma unroll
        for (int j = 0; j < 4; j++) {
            int best = -1;
            float bvv = -3.4e38f; int be = 0x7fffffff;
            for (int t = 0; t < NCAND; t++) {
                if (used[t]) continue;
                if (s_sim[t] > bvv || (s_sim[t] == bvv && s_e[t] < be)) {
                    bvv = s_sim[t]; be = s_e[t]; best = t;
                }
            }
            used[best] = true;
            g_topk[(b * NREF + r) * 4 + j] = s_e[best];
        }
    }
}

// ---------------------------------------------------------------------------
// K3: KL + smooth-L1 losses, 64 threads per row-pair, fast-math exp/log;
//     last-arriving block writes the final scalar.
// ---------------------------------------------------------------------------
__global__ void __launch_bounds__(256)
k_loss(const float* __restrict__ teacher, const float* __restrict__ student,
       const int* __restrict__ ref_perm, const int* __restrict__ shared_perm,
       float* __restrict__ out) {
    __shared__ float sacc[3];
    __shared__ float r0[4][2], r1[4][2];
    int tid = threadIdx.x;
    if (tid < 3) sacc[tid] = 0.f;

    int grp  = tid >> 6;
    int sub  = tid & 63;
    int w2   = (tid >> 5) & 1;
    int lane = tid & 31;
    int w    = blockIdx.x * 4 + grp;

    const float *pa, *pb, *pc, *pd;
    int target;
    if (w < 1536) {
        target = 0;
        int i = w / 512, rem = w & 511;
        int b = rem >> 8, r = rem & 255;
        int rp = ref_perm[r], sp = shared_perm[r];
        pa = teacher + ((size_t)(b * VDIM) * PDIM + rp) * DDIM;
        pb = teacher + ((size_t)(b * VDIM + c_ST[i]) * PDIM + sp) * DDIM;
        pc = student + ((size_t)(b * 4) * PDIM + rp) * DDIM;
        pd = student + ((size_t)(b * 4 + c_SS[i]) * PDIM + sp) * DDIM;
    } else if (w < 3584) {
        target = 1;
        int t = w - 1536;
        int b = t >> 10, rem = t & 1023;
        int r = rem >> 2, k = rem & 3;
        int rp = ref_perm[r];
        int e = g_topk[((b << 8) + r) * 4 + k];
        int v = 2 * (e >> 12) + 1, p = e & (PDIM - 1);
        pa = teacher + ((size_t)(b * VDIM) * PDIM + rp) * DDIM;
        pc = student + ((size_t)(b * 4) * PDIM + rp) * DDIM;
        pb = pd = teacher + ((size_t)(b * VDIM + v) * PDIM + p) * DDIM;
    } else {
        target = 2;
        int t = w - 3584;
        int i = t >> 11, rem = t & 2047;
        int b = rem >> 10, r = (rem >> 2) & 255, k = rem & 3;
        int sp = shared_perm[r];
        int e = g_topk[((b << 8) + r) * 4 + k];
        int v = 2 * (e >> 12) + 1, p = e & (PDIM - 1);
        pa = teacher + ((size_t)(b * VDIM + c_ST[i]) * PDIM + sp) * DDIM;
        pc = student + ((size_t)(b * 4 + c_SS[i]) * PDIM + sp) * DDIM;
        pb = pd = teacher + ((size_t)(b * VDIM + v) * PDIM + p) * DDIM;
    }

    float dt[16], ds[16];
    bool same = (pb == pd);
    #pragma unroll
    for (int j = 0; j < 4; j++) {
        int idx = sub * 4 + j * 256;
        float4 A  = *(const float4*)(pa + idx);
        float4 Bv = *(const float4*)(pb + idx);
        float4 C  = *(const float4*)(pc + idx);
        float4 Dv = same ? Bv : *(const float4*)(pd + idx);
        dt[4 * j + 0] = A.x - Bv.x; dt[4 * j + 1] = A.y - Bv.y;
        dt[4 * j + 2] = A.z - Bv.z; dt[4 * j + 3] = A.w - Bv.w;
        ds[4 * j + 0] = C.x - Dv.x; ds[4 * j + 1] = C.y - Dv.y;
        ds[4 * j + 2] = C.z - Dv.z; ds[4 * j + 3] = C.w - Dv.w;
    }

    float mt = -3.4e38f, ms = -3.4e38f;
    #pragma unroll
    for (int i = 0; i < 16; i++) { mt = fmaxf(mt, dt[i]); ms = fmaxf(ms, ds[i]); }
    #pragma unroll
    for (int o = 16; o; o >>= 1) {
        mt = fmaxf(mt, __shfl_xor_sync(0xffffffffu, mt, o));
        ms = fmaxf(ms, __shfl_xor_sync(0xffffffffu, ms, o));
    }
    if (lane == 0) { r0[grp][w2] = mt; r1[grp][w2] = ms; }
    __syncthreads();
    mt = fmaxf(r0[grp][0], r0[grp][1]);
    ms = fmaxf(r1[grp][0], r1[grp][1]);

    float st = 0.f, ssum = 0.f;
    #pragma unroll
    for (int i = 0; i < 16; i++) { st += __expf(dt[i] - mt); ssum += __expf(ds[i] - ms); }
    #pragma unroll
    for (int o = 16; o; o >>= 1) {
        st   += __shfl_xor_sync(0xffffffffu, st, o);
        ssum += __shfl_xor_sync(0xffffffffu, ssum, o);
    }
    __syncthreads();
    if (lane == 0) { r0[grp][w2] = st; r1[grp][w2] = ssum; }
    __syncthreads();
    float lset = mt + __logf(r0[grp][0] + r0[grp][1]);
    float lses = ms + __logf(r1[grp][0] + r1[grp][1]);

    float acc = 0.f;
    #pragma unroll
    for (int i = 0; i < 16; i++) acc += __expf(dt[i] - lset) * (dt[i] - ds[i]);
    #pragma unroll
    for (int o = 16; o; o >>= 1) acc += __shfl_xor_sync(0xffffffffu, acc, o);
    __syncthreads();
    if (lane == 0) r0[grp][w2] = acc;
    __syncthreads();

    if (sub == 0) {
        float kl = (r0[grp][0] + r0[grp][1]) - lset + lses;
        float ax = fabsf(kl);
        float sl = (ax < 0.5f) ? kl * kl : (ax - 0.25f);   // smooth_l1, beta=0.5
        atomicAdd(&sacc[target], sl);
    }
    __syncthreads();
    if (tid < 3) atomicAdd(&g_accum[tid], sacc[tid]);

    // last-arriving block folds the final combine
    __syncthreads();
    if (tid == 0) {
        __threadfence();
        unsigned t = atomicAdd(&g_done, 1);
        if (t == gridDim.x - 1) {
            __threadfence();
            out[0] = g_accum[0] * (1.0f / 1536.0f)
                   + g_accum[1] * (1.0f / 2048.0f)
                   + g_accum[2] * (1.0f / 6144.0f);
            g_done = 0;
        }
    }
}

// ---------------------------------------------------------------------------
extern "C" void kernel_launch(void* const* d_in, const int* in_sizes, int n_in,
                              void* d_out, int out_size) {
    const float* teacher     = (const float*)d_in[0];
    const float* student     = (const float*)d_in[1];
    const int*   ref_perm    = (const int*)d_in[2];
    const int*   shared_perm = (const int*)d_in[3];
    float* out = (float*)d_out;

    cudaFuncSetAttribute(k_gemm, cudaFuncAttributeMaxDynamicSharedMemorySize, GEMM_SMEM);

    k_convert<<<BDIM * NREF, 128>>>(teacher, ref_perm);
    k_gemm<<<dim3(EN / 64, 1, BDIM), 256, GEMM_SMEM>>>(teacher);
    k_select<<<dim3(NREF, BDIM), 256>>>(teacher, ref_perm);
    k_loss<<<9728 / 4, 256>>>(teacher, student, ref_perm, shared_perm, out);
}